// round 1
// baseline (speedup 1.0000x reference)
#include <cuda_runtime.h>
#include <math.h>
#include <stdint.h>

// Problem constants
#define BB 32
#define SS 512
#define DD 1024
#define HH 16
#define DH 64
#define LL 4
#define DFF 2048
#define DMEM 512
#define TT (BB * SS)   // 16384 tokens

// ---------------------------------------------------------------------------
// Scratch (static device globals — no allocation at runtime)
// ---------------------------------------------------------------------------
__device__ float g_h[(size_t)TT * DD];          //  64 MB  [S,B,D] token-major (row = s*B+b)
__device__ float g_qkv[(size_t)TT * 3 * DD];    // 192 MB
__device__ float g_ctx[(size_t)TT * DD];        //  64 MB
__device__ float g_tmp[(size_t)TT * DD];        //  64 MB
__device__ float g_ff[(size_t)TT * DFF];        // 128 MB

// ---------------------------------------------------------------------------
// Packed f32x2 helpers (Blackwell f32x2 FMA: 2x scalar FFMA throughput)
// ---------------------------------------------------------------------------
__device__ __forceinline__ unsigned long long pack2(float lo, float hi) {
    unsigned long long r;
    asm("mov.b64 %0, {%1, %2};" : "=l"(r) : "f"(lo), "f"(hi));
    return r;
}
__device__ __forceinline__ unsigned long long fma2(unsigned long long a,
                                                   unsigned long long b,
                                                   unsigned long long c) {
    unsigned long long d;
    asm("fma.rn.f32x2 %0, %1, %2, %3;" : "=l"(d) : "l"(a), "l"(b), "l"(c));
    return d;
}
__device__ __forceinline__ float2 unpack2(unsigned long long v) {
    float2 f;
    asm("mov.b64 {%0, %1}, %2;" : "=f"(f.x), "=f"(f.y) : "l"(v));
    return f;
}

// ---------------------------------------------------------------------------
// 1) h[s,b,:] = x[b,s,:] + PE(s,:)
// ---------------------------------------------------------------------------
__global__ __launch_bounds__(256)
void add_pe_kernel(const float* __restrict__ x, float* __restrict__ h) {
    int idx = blockIdx.x * blockDim.x + threadIdx.x;      // over TT*DD
    int d   = idx & (DD - 1);
    int row = idx >> 10;          // s*B + b
    int s   = row >> 5;           // / 32
    int b   = row & 31;
    float div = expf((float)(d & ~1) * (-9.2103403719761836f / (float)DD));
    float ang = (float)s * div;
    float pe  = (d & 1) ? cosf(ang) : sinf(ang);
    h[idx] = x[((size_t)(b * SS + s) << 10) + d] + pe;
}

// ---------------------------------------------------------------------------
// 2) SGEMM: C[M,N] = A[M,K] @ W[N,K]^T + bias[N]   (opt ReLU, opt A-row perm)
//    Tiles: 128x128x8, 256 threads, 8x8 per-thread micro-tile, f32x2 FMA.
//    PERM: A source row for output row m=(b*S+s) is (s*B+b) — fuses transpose.
// ---------------------------------------------------------------------------
template <int RELU, int PERM>
__global__ __launch_bounds__(256)
void sgemm_kernel(const float* __restrict__ A, const float* __restrict__ W,
                  const float* __restrict__ bias, float* __restrict__ C,
                  int M, int N, int K) {
    __shared__ float As[8][128];
    __shared__ float Ws[8][128];
    const int t  = threadIdx.x;
    const int m0 = blockIdx.y * 128;
    const int n0 = blockIdx.x * 128;
    const int tn = (t & 15) * 8;   // n offset within tile
    const int tm = (t >> 4) * 8;   // m offset within tile
    const int lrow = t >> 1;       // 0..127
    const int lcol = (t & 1) * 4;  // 0 or 4

    int arow = m0 + lrow;
    if (PERM) arow = (arow & 511) * 32 + (arow >> 9);
    const float* Ap = A + (size_t)arow * K + lcol;
    const float* Wp = W + (size_t)(n0 + lrow) * K + lcol;

    unsigned long long acc[8][4];
#pragma unroll
    for (int i = 0; i < 8; i++)
#pragma unroll
        for (int j = 0; j < 4; j++) acc[i][j] = 0ull;

    for (int k0 = 0; k0 < K; k0 += 8) {
        float4 av = *reinterpret_cast<const float4*>(Ap + k0);
        float4 wv = *reinterpret_cast<const float4*>(Wp + k0);
        __syncthreads();
        As[lcol + 0][lrow] = av.x; As[lcol + 1][lrow] = av.y;
        As[lcol + 2][lrow] = av.z; As[lcol + 3][lrow] = av.w;
        Ws[lcol + 0][lrow] = wv.x; Ws[lcol + 1][lrow] = wv.y;
        Ws[lcol + 2][lrow] = wv.z; Ws[lcol + 3][lrow] = wv.w;
        __syncthreads();
#pragma unroll
        for (int k = 0; k < 8; k++) {
            float4 a0 = *reinterpret_cast<const float4*>(&As[k][tm]);
            float4 a1 = *reinterpret_cast<const float4*>(&As[k][tm + 4]);
            float4 b0 = *reinterpret_cast<const float4*>(&Ws[k][tn]);
            float4 b1 = *reinterpret_cast<const float4*>(&Ws[k][tn + 4]);
            unsigned long long bp[4] = {pack2(b0.x, b0.y), pack2(b0.z, b0.w),
                                        pack2(b1.x, b1.y), pack2(b1.z, b1.w)};
            float aa[8] = {a0.x, a0.y, a0.z, a0.w, a1.x, a1.y, a1.z, a1.w};
#pragma unroll
            for (int i = 0; i < 8; i++) {
                unsigned long long ap = pack2(aa[i], aa[i]);
#pragma unroll
                for (int j = 0; j < 4; j++) acc[i][j] = fma2(ap, bp[j], acc[i][j]);
            }
        }
    }

    float bj[8];
#pragma unroll
    for (int j = 0; j < 8; j++) bj[j] = bias[n0 + tn + j];
#pragma unroll
    for (int i = 0; i < 8; i++) {
        float2 p0 = unpack2(acc[i][0]);
        float2 p1 = unpack2(acc[i][1]);
        float2 p2 = unpack2(acc[i][2]);
        float2 p3 = unpack2(acc[i][3]);
        float4 v0 = make_float4(p0.x + bj[0], p0.y + bj[1], p1.x + bj[2], p1.y + bj[3]);
        float4 v1 = make_float4(p2.x + bj[4], p2.y + bj[5], p3.x + bj[6], p3.y + bj[7]);
        if (RELU) {
            v0.x = fmaxf(v0.x, 0.f); v0.y = fmaxf(v0.y, 0.f);
            v0.z = fmaxf(v0.z, 0.f); v0.w = fmaxf(v0.w, 0.f);
            v1.x = fmaxf(v1.x, 0.f); v1.y = fmaxf(v1.y, 0.f);
            v1.z = fmaxf(v1.z, 0.f); v1.w = fmaxf(v1.w, 0.f);
        }
        float* crow = C + (size_t)(m0 + tm + i) * N + n0 + tn;
        *reinterpret_cast<float4*>(crow)     = v0;
        *reinterpret_cast<float4*>(crow + 4) = v1;
    }
}

// ---------------------------------------------------------------------------
// 3) Fused flash attention: block = (q-tile of 64, one (b,h)), online softmax.
//    qkv layout: [S,B,3D], q at +0, k at +1024, v at +2048, head h at h*64.
// ---------------------------------------------------------------------------
#define BQ 64
#define BKT 32
__global__ __launch_bounds__(256)
void attn_kernel(const float* __restrict__ qkv, float* __restrict__ ctx) {
    __shared__ float Qs[BQ][DH + 1];     // pre-scaled Q
    __shared__ float Ks[BKT][DH + 2];
    __shared__ float Vs[BKT][DH + 2];
    __shared__ float Ss[BQ][BKT + 2];
    __shared__ float m_sh[BQ], l_sh[BQ], al_sh[BQ];

    const int t  = threadIdx.x;       // 256
    const int tx = t & 15;
    const int ty = t >> 4;
    const int b  = blockIdx.y >> 4;   // H = 16
    const int h  = blockIdx.y & 15;
    const int q0 = blockIdx.x * BQ;
    const int hd = h * DH;

#pragma unroll
    for (int p = 0; p < (BQ * DH) / 256; ++p) {   // 16 passes
        int idx = t + p * 256;
        int r = idx >> 6, d = idx & 63;
        Qs[r][d] = qkv[((size_t)((q0 + r) * BB + b)) * 3072 + hd + d] * 0.125f;
    }
    if (t < BQ) { m_sh[t] = -1e30f; l_sh[t] = 0.f; }

    float O[4][4];
#pragma unroll
    for (int i = 0; i < 4; i++)
#pragma unroll
        for (int j = 0; j < 4; j++) O[i][j] = 0.f;
    __syncthreads();

    for (int kt = 0; kt < SS / BKT; ++kt) {        // 16 iterations
#pragma unroll
        for (int p = 0; p < (BKT * DH) / 256; ++p) {  // 8 passes
            int idx = t + p * 256;
            int r = idx >> 6, d = idx & 63;
            size_t base = ((size_t)((kt * BKT + r) * BB + b)) * 3072 + hd + d;
            Ks[r][d] = qkv[base + 1024];
            Vs[r][d] = qkv[base + 2048];
        }
        __syncthreads();

        // S tile [64 x 32]: rows ty*4+i, cols tx*2+jj
        float sacc[4][2] = {{0.f, 0.f}, {0.f, 0.f}, {0.f, 0.f}, {0.f, 0.f}};
#pragma unroll
        for (int d = 0; d < DH; ++d) {
            float k0v = Ks[tx * 2 + 0][d];
            float k1v = Ks[tx * 2 + 1][d];
#pragma unroll
            for (int i = 0; i < 4; i++) {
                float qv = Qs[ty * 4 + i][d];
                sacc[i][0] += qv * k0v;
                sacc[i][1] += qv * k1v;
            }
        }
#pragma unroll
        for (int i = 0; i < 4; i++) {
            Ss[ty * 4 + i][tx * 2 + 0] = sacc[i][0];
            Ss[ty * 4 + i][tx * 2 + 1] = sacc[i][1];
        }
        __syncthreads();

        // Online softmax, one row per thread (t < 64)
        if (t < BQ) {
            float mprev = m_sh[t];
            float mx = mprev;
            for (int j = 0; j < BKT; j++) mx = fmaxf(mx, Ss[t][j]);
            float al = expf(mprev - mx);
            float sum = 0.f;
            for (int j = 0; j < BKT; j++) {
                float p = expf(Ss[t][j] - mx);
                Ss[t][j] = p;
                sum += p;
            }
            m_sh[t]  = mx;
            l_sh[t]  = l_sh[t] * al + sum;
            al_sh[t] = al;
        }
        __syncthreads();

        // O = O*alpha + P @ V
#pragma unroll
        for (int i = 0; i < 4; i++) {
            float al = al_sh[ty * 4 + i];
            float pv[4] = {0.f, 0.f, 0.f, 0.f};
            for (int k = 0; k < BKT; k++) {
                float p = Ss[ty * 4 + i][k];
#pragma unroll
                for (int j = 0; j < 4; j++) pv[j] += p * Vs[k][tx * 4 + j];
            }
#pragma unroll
            for (int j = 0; j < 4; j++) O[i][j] = O[i][j] * al + pv[j];
        }
        __syncthreads();
    }

#pragma unroll
    for (int i = 0; i < 4; i++) {
        int r = ty * 4 + i;
        float invl = 1.f / l_sh[r];
#pragma unroll
        for (int j = 0; j < 4; j++)
            ctx[((size_t)((q0 + r) * BB + b)) * 1024 + hd + tx * 4 + j] = O[i][j] * invl;
    }
}

// ---------------------------------------------------------------------------
// 4) LayerNorm: out = LN(a [+ r]) * g + b   — one block per token row, D=1024
// ---------------------------------------------------------------------------
__global__ __launch_bounds__(256)
void ln_kernel(const float* __restrict__ a, const float* __restrict__ r,
               const float* __restrict__ g, const float* __restrict__ b,
               float* __restrict__ out) {
    __shared__ float red[256];
    const int t = threadIdx.x;
    const size_t row = blockIdx.x;
    float4 v = reinterpret_cast<const float4*>(a + row * 1024)[t];
    if (r != nullptr) {
        float4 rv = reinterpret_cast<const float4*>(r + row * 1024)[t];
        v.x += rv.x; v.y += rv.y; v.z += rv.z; v.w += rv.w;
    }
    red[t] = v.x + v.y + v.z + v.w;
    __syncthreads();
    for (int o = 128; o > 0; o >>= 1) {
        if (t < o) red[t] += red[t + o];
        __syncthreads();
    }
    float mu = red[0] * (1.f / 1024.f);
    __syncthreads();
    float dx = v.x - mu, dy = v.y - mu, dz = v.z - mu, dw = v.w - mu;
    red[t] = dx * dx + dy * dy + dz * dz + dw * dw;
    __syncthreads();
    for (int o = 128; o > 0; o >>= 1) {
        if (t < o) red[t] += red[t + o];
        __syncthreads();
    }
    float inv = rsqrtf(red[0] * (1.f / 1024.f) + 1e-5f);
    float4 g4 = reinterpret_cast<const float4*>(g)[t];
    float4 b4 = reinterpret_cast<const float4*>(b)[t];
    float4 o4;
    o4.x = dx * inv * g4.x + b4.x;
    o4.y = dy * inv * g4.y + b4.y;
    o4.z = dz * inv * g4.z + b4.z;
    o4.w = dw * inv * g4.w + b4.w;
    reinterpret_cast<float4*>(out + row * 1024)[t] = o4;
}

// ---------------------------------------------------------------------------
// Host orchestration (graph-capturable: kernel launches only)
// ---------------------------------------------------------------------------
extern "C" void kernel_launch(void* const* d_in, const int* in_sizes, int n_in,
                              void* d_out, int out_size) {
    (void)in_sizes; (void)n_in; (void)out_size;
    const float* x    = (const float*)d_in[0];
    const float* Wqkv = (const float*)d_in[1];
    const float* bqkv = (const float*)d_in[2];
    const float* Wo   = (const float*)d_in[3];
    const float* bo   = (const float*)d_in[4];
    const float* W1   = (const float*)d_in[5];
    const float* b1   = (const float*)d_in[6];
    const float* W2   = (const float*)d_in[7];
    const float* b2   = (const float*)d_in[8];
    const float* ln1g = (const float*)d_in[9];
    const float* ln1b = (const float*)d_in[10];
    const float* ln2g = (const float*)d_in[11];
    const float* ln2b = (const float*)d_in[12];
    const float* lnfg = (const float*)d_in[13];
    const float* lnfb = (const float*)d_in[14];
    const float* Wout = (const float*)d_in[15];
    const float* bout = (const float*)d_in[16];
    float* out = (float*)d_out;

    float *h, *qkv, *ctx, *tmp, *ff;
    cudaGetSymbolAddress((void**)&h,   g_h);
    cudaGetSymbolAddress((void**)&qkv, g_qkv);
    cudaGetSymbolAddress((void**)&ctx, g_ctx);
    cudaGetSymbolAddress((void**)&tmp, g_tmp);
    cudaGetSymbolAddress((void**)&ff,  g_ff);

    // h = transpose(x) + PE
    add_pe_kernel<<<(TT * DD) / 256, 256>>>(x, h);

    for (int l = 0; l < LL; l++) {
        const float* wqkv_l = Wqkv + (size_t)l * 3072 * 1024;
        const float* bqkv_l = bqkv + (size_t)l * 3072;
        const float* wo_l   = Wo   + (size_t)l * 1024 * 1024;
        const float* bo_l   = bo   + (size_t)l * 1024;
        const float* w1_l   = W1   + (size_t)l * 2048 * 1024;
        const float* b1_l   = b1   + (size_t)l * 2048;
        const float* w2_l   = W2   + (size_t)l * 1024 * 2048;
        const float* b2_l   = b2   + (size_t)l * 1024;

        // qkv = h @ Wqkv^T + bqkv
        sgemm_kernel<0, 0><<<dim3(3072 / 128, TT / 128), 256>>>(
            h, wqkv_l, bqkv_l, qkv, TT, 3072, 1024);
        // ctx = softmax(q k^T / sqrt(dh)) v   (fused, online softmax)
        attn_kernel<<<dim3(SS / BQ, BB * HH), 256>>>(qkv, ctx);
        // sa = ctx @ Wo^T + bo
        sgemm_kernel<0, 0><<<dim3(1024 / 128, TT / 128), 256>>>(
            ctx, wo_l, bo_l, tmp, TT, 1024, 1024);
        // h = LN(h + sa)
        ln_kernel<<<TT, 256>>>(h, tmp, ln1g + l * 1024, ln1b + l * 1024, h);
        // ff = relu(h @ W1^T + b1)
        sgemm_kernel<1, 0><<<dim3(2048 / 128, TT / 128), 256>>>(
            h, w1_l, b1_l, ff, TT, 2048, 1024);
        // ff2 = ff @ W2^T + b2
        sgemm_kernel<0, 0><<<dim3(1024 / 128, TT / 128), 256>>>(
            ff, w2_l, b2_l, tmp, TT, 1024, 2048);
        // h = LN(h + ff2)
        ln_kernel<<<TT, 256>>>(h, tmp, ln2g + l * 1024, ln2b + l * 1024, h);
    }

    // final norm
    ln_kernel<<<TT, 256>>>(h, nullptr, lnfg, lnfb, h);
    // out[b,s,:] = h[s,b,:] @ Wout^T + bout  (PERM fuses the transpose)
    sgemm_kernel<0, 1><<<dim3(DMEM / 128, TT / 128), 256>>>(
        h, Wout, bout, out, TT, DMEM, 1024);
}

// round 3
// speedup vs baseline: 1.7507x; 1.7507x over previous
#include <cuda_runtime.h>
#include <cuda_bf16.h>
#include <math.h>
#include <stdint.h>

// Problem constants
#define BBB 32
#define SSS 512
#define DDD 1024
#define HHH 16
#define DHH 64
#define LLL 4
#define DFFF 2048
#define DMEMM 512
#define TTT (BBB * SSS)   // 16384 tokens

// ---------------------------------------------------------------------------
// Scratch (static device globals — no allocation at runtime)
// ---------------------------------------------------------------------------
__device__ float g_h[(size_t)TTT * DDD];            //  64 MB  [S,B,D] token-major
__device__ float g_qkv[(size_t)TTT * 3 * DDD];      // 192 MB
__device__ float g_tmp[(size_t)TTT * DDD];          //  64 MB
__device__ __nv_bfloat16 g_hhi[(size_t)TTT * DDD];  //  32 MB  h split
__device__ __nv_bfloat16 g_hlo[(size_t)TTT * DDD];
__device__ __nv_bfloat16 g_bhi[(size_t)TTT * DFFF]; //  64 MB  ctx / ff split
__device__ __nv_bfloat16 g_blo[(size_t)TTT * DFFF];
#define WTOT 34078720ULL
__device__ __nv_bfloat16 g_whi[WTOT];               //  68 MB  all weights hi
__device__ __nv_bfloat16 g_wlo[WTOT];               //  68 MB  all weights lo

// Weight offsets in split buffer (elements)
#define OFF_QKV 0ULL
#define OFF_WO  12582912ULL
#define OFF_W1  16777216ULL
#define OFF_W2  25165824ULL
#define OFF_WOUT 33554432ULL

// ---------------------------------------------------------------------------
// PTX helpers (baseline sm_80+: mma.sync / ldmatrix / cp.async)
// ---------------------------------------------------------------------------
__device__ __forceinline__ uint32_t smem_u32(const void* p) {
    uint32_t a;
    asm("{ .reg .u64 t; cvta.to.shared.u64 t, %1; cvt.u32.u64 %0, t; }" : "=r"(a) : "l"(p));
    return a;
}

#define CP16(saddr, gptr) \
    asm volatile("cp.async.cg.shared.global [%0], [%1], 16;" :: "r"(saddr), "l"(gptr))
#define CPCOMMIT() asm volatile("cp.async.commit_group;" ::: "memory")
#define CPWAIT(n)  asm volatile("cp.async.wait_group %0;" :: "n"(n) : "memory")

#define LDSM4(r, addr)                                                          \
    asm volatile("ldmatrix.sync.aligned.m8n8.x4.shared.b16 {%0,%1,%2,%3}, [%4];" \
        : "=r"((r)[0]), "=r"((r)[1]), "=r"((r)[2]), "=r"((r)[3]) : "r"(addr))

#define MMA_BF16(d, a, b0v, b1v)                                                \
    asm volatile("mma.sync.aligned.m16n8k16.row.col.f32.bf16.bf16.f32 "         \
        "{%0,%1,%2,%3}, {%4,%5,%6,%7}, {%8,%9}, {%0,%1,%2,%3};"                 \
        : "+f"((d)[0]), "+f"((d)[1]), "+f"((d)[2]), "+f"((d)[3])                \
        : "r"((a)[0]), "r"((a)[1]), "r"((a)[2]), "r"((a)[3]), "r"(b0v), "r"(b1v))

// bf16 split helper
__device__ __forceinline__ void split_bf16(float v, __nv_bfloat16& h, __nv_bfloat16& l) {
    h = __float2bfloat16(v);
    l = __float2bfloat16(v - __bfloat162float(h));
}

// ---------------------------------------------------------------------------
// 0) weight split: fp32 -> (hi, lo) bf16
// ---------------------------------------------------------------------------
__global__ __launch_bounds__(256)
void cvt_split_kernel(const float* __restrict__ in, __nv_bfloat16* __restrict__ hi,
                      __nv_bfloat16* __restrict__ lo, int n4) {
    int i = blockIdx.x * 256 + threadIdx.x;
    if (i >= n4) return;
    float4 v = reinterpret_cast<const float4*>(in)[i];
    __nv_bfloat16 h0, h1, h2, h3, l0, l1, l2, l3;
    split_bf16(v.x, h0, l0); split_bf16(v.y, h1, l1);
    split_bf16(v.z, h2, l2); split_bf16(v.w, h3, l3);
    __nv_bfloat162 a, b;
    a.x = h0; a.y = h1; b.x = h2; b.y = h3;
    reinterpret_cast<__nv_bfloat162*>(hi)[2 * i]     = a;
    reinterpret_cast<__nv_bfloat162*>(hi)[2 * i + 1] = b;
    a.x = l0; a.y = l1; b.x = l2; b.y = l3;
    reinterpret_cast<__nv_bfloat162*>(lo)[2 * i]     = a;
    reinterpret_cast<__nv_bfloat162*>(lo)[2 * i + 1] = b;
}

// ---------------------------------------------------------------------------
// 1) h[s,b,:] = x[b,s,:] + PE(s,:)   (+ split emit)
// ---------------------------------------------------------------------------
__global__ __launch_bounds__(256)
void add_pe_kernel(const float* __restrict__ x, float* __restrict__ h,
                   __nv_bfloat16* __restrict__ hhi, __nv_bfloat16* __restrict__ hlo) {
    int idx = blockIdx.x * blockDim.x + threadIdx.x;
    int d   = idx & (DDD - 1);
    int row = idx >> 10;
    int s   = row >> 5;
    int b   = row & 31;
    float div = expf((float)(d & ~1) * (-9.2103403719761836f / (float)DDD));
    float ang = (float)s * div;
    float pe  = (d & 1) ? cosf(ang) : sinf(ang);
    float v = x[((size_t)(b * SSS + s) << 10) + d] + pe;
    h[idx] = v;
    __nv_bfloat16 hh, ll;
    split_bf16(v, hh, ll);
    hhi[idx] = hh; hlo[idx] = ll;
}

// ---------------------------------------------------------------------------
// 2) HMMA GEMM: C[M,N] = (Ahi+Alo)[M,K] @ (Whi+Wlo)[N,K]^T + bias  (bf16x3)
//    BM=128, BN=128, BK=32, 256 thr (8 warps 2x4), warp tile 64x32,
//    cp.async double-buffered, ldmatrix.x4, mma.sync.m16n8k16.
//    smem rows padded to 40 elems (80B) -> conflict-free ldmatrix.
// ---------------------------------------------------------------------------
#define SROW 40          // padded row, elements
#define SROWB 80         // bytes
#define BUF_B 10240      // one 128x32 bf16 buffer (padded)
#define A_HI 0u
#define A_LO 10240u
#define W_HI 20480u
#define W_LO 30720u
#define STAGE_B 40960u
#define GEMM_SMEM (2 * 40960)

template <int PERM>
__device__ __forceinline__ void load_stage(
    uint32_t sbase,
    const __nv_bfloat16* __restrict__ Ahi, const __nv_bfloat16* __restrict__ Alo,
    const __nv_bfloat16* __restrict__ Whi, const __nv_bfloat16* __restrict__ Wlo,
    int m0, int n0, int K, int k0, int t) {
#pragma unroll
    for (int i = 0; i < 2; ++i) {
        int u = t + i * 256;              // 0..511
        int row = u >> 2, c8 = u & 3;
        int garow = m0 + row;
        if (PERM) garow = ((garow & 511) << 5) | (garow >> 9);
        const __nv_bfloat16* pa_hi = Ahi + (size_t)garow * K + k0 + c8 * 8;
        const __nv_bfloat16* pa_lo = Alo + (size_t)garow * K + k0 + c8 * 8;
        const __nv_bfloat16* pw_hi = Whi + (size_t)(n0 + row) * K + k0 + c8 * 8;
        const __nv_bfloat16* pw_lo = Wlo + (size_t)(n0 + row) * K + k0 + c8 * 8;
        uint32_t d = (uint32_t)(row * SROWB + c8 * 16);
        CP16(sbase + A_HI + d, pa_hi);
        CP16(sbase + A_LO + d, pa_lo);
        CP16(sbase + W_HI + d, pw_hi);
        CP16(sbase + W_LO + d, pw_lo);
    }
}

template <int RELU, int PERM, int SPLIT>
__global__ __launch_bounds__(256)
void gemm_mma(const __nv_bfloat16* __restrict__ Ahi, const __nv_bfloat16* __restrict__ Alo,
              const __nv_bfloat16* __restrict__ Whi, const __nv_bfloat16* __restrict__ Wlo,
              const float* __restrict__ bias, float* __restrict__ C,
              __nv_bfloat16* __restrict__ Chi, __nv_bfloat16* __restrict__ Clo,
              int M, int N, int K) {
    extern __shared__ char smem[];
    const uint32_t sb = smem_u32(smem);
    const int t    = threadIdx.x;
    const int lane = t & 31;
    const int w    = t >> 5;
    const int wm   = w & 1;          // 2 m-warps
    const int wn   = w >> 1;         // 4 n-warps
    const int m0   = blockIdx.y * 128;
    const int n0   = blockIdx.x * 128;

    float acc[4][4][4];
#pragma unroll
    for (int a = 0; a < 4; a++)
#pragma unroll
        for (int b = 0; b < 4; b++)
#pragma unroll
            for (int c = 0; c < 4; c++) acc[a][b][c] = 0.f;

    // ldmatrix per-thread base offsets (bytes within a buffer)
    const uint32_t a_off = (uint32_t)((wm * 64 + (lane & 15)) * SROWB + (lane >> 4) * 16);
    const int brow = wn * 32 + (lane & 7) + ((lane & 16) >> 1);
    const uint32_t b_off = (uint32_t)(brow * SROWB + ((lane >> 3) & 1) * 16);

    const int NC = K >> 5;
    load_stage<PERM>(sb, Ahi, Alo, Whi, Wlo, m0, n0, K, 0, t);
    CPCOMMIT();

    for (int c = 0; c < NC; ++c) {
        const uint32_t stb = sb + (uint32_t)(c & 1) * STAGE_B;
        if (c + 1 < NC) {
            load_stage<PERM>(sb + (uint32_t)((c + 1) & 1) * STAGE_B,
                             Ahi, Alo, Whi, Wlo, m0, n0, K, (c + 1) << 5, t);
            CPCOMMIT();
            CPWAIT(1);
        } else {
            CPWAIT(0);
        }
        __syncthreads();
#pragma unroll
        for (int ks = 0; ks < 2; ++ks) {
            const uint32_t ao = stb + a_off + ks * 32;
            const uint32_t bo = stb + b_off + ks * 32;
            uint32_t fa_hi[4][4], fa_lo[4][4];
#pragma unroll
            for (int mi = 0; mi < 4; ++mi) {
                LDSM4(fa_hi[mi], ao + A_HI + mi * (16 * SROWB));
                LDSM4(fa_lo[mi], ao + A_LO + mi * (16 * SROWB));
            }
            uint32_t fb_hi[2][4], fb_lo[2][4];
#pragma unroll
            for (int nj = 0; nj < 2; ++nj) {
                LDSM4(fb_hi[nj], bo + W_HI + nj * (16 * SROWB));
                LDSM4(fb_lo[nj], bo + W_LO + nj * (16 * SROWB));
            }
#pragma unroll
            for (int mi = 0; mi < 4; ++mi)
#pragma unroll
                for (int ni = 0; ni < 4; ++ni) {
                    const int nj = ni >> 1, kk = (ni & 1) * 2;
                    MMA_BF16(acc[mi][ni], fa_hi[mi], fb_hi[nj][kk], fb_hi[nj][kk + 1]);
                    MMA_BF16(acc[mi][ni], fa_hi[mi], fb_lo[nj][kk], fb_lo[nj][kk + 1]);
                    MMA_BF16(acc[mi][ni], fa_lo[mi], fb_hi[nj][kk], fb_hi[nj][kk + 1]);
                }
        }
        __syncthreads();
    }

    // ---- epilogue ----
    const int qrow = lane >> 2;      // 0..7
    const int qcol = (lane & 3) * 2; // 0,2,4,6
#pragma unroll
    for (int mi = 0; mi < 4; ++mi) {
        const int row0 = m0 + wm * 64 + mi * 16 + qrow;
#pragma unroll
        for (int ni = 0; ni < 4; ++ni) {
            const int col = n0 + wn * 32 + ni * 8 + qcol;
            const float bb0 = bias[col];
            const float bb1 = bias[col + 1];
            float v00 = acc[mi][ni][0] + bb0;
            float v01 = acc[mi][ni][1] + bb1;
            float v10 = acc[mi][ni][2] + bb0;
            float v11 = acc[mi][ni][3] + bb1;
            if (RELU) {
                v00 = fmaxf(v00, 0.f); v01 = fmaxf(v01, 0.f);
                v10 = fmaxf(v10, 0.f); v11 = fmaxf(v11, 0.f);
            }
            if (SPLIT) {
                __nv_bfloat16 h0, l0, h1, l1;
                __nv_bfloat162 hh, ll;
                split_bf16(v00, h0, l0); split_bf16(v01, h1, l1);
                hh.x = h0; hh.y = h1; ll.x = l0; ll.y = l1;
                *reinterpret_cast<__nv_bfloat162*>(Chi + (size_t)row0 * N + col) = hh;
                *reinterpret_cast<__nv_bfloat162*>(Clo + (size_t)row0 * N + col) = ll;
                split_bf16(v10, h0, l0); split_bf16(v11, h1, l1);
                hh.x = h0; hh.y = h1; ll.x = l0; ll.y = l1;
                *reinterpret_cast<__nv_bfloat162*>(Chi + (size_t)(row0 + 8) * N + col) = hh;
                *reinterpret_cast<__nv_bfloat162*>(Clo + (size_t)(row0 + 8) * N + col) = ll;
            } else {
                *reinterpret_cast<float2*>(C + (size_t)row0 * N + col) =
                    make_float2(v00, v01);
                *reinterpret_cast<float2*>(C + (size_t)(row0 + 8) * N + col) =
                    make_float2(v10, v11);
            }
        }
    }
}

// ---------------------------------------------------------------------------
// 3) Fused flash attention (fp32 compute; epilogue emits bf16 split ctx)
// ---------------------------------------------------------------------------
#define BQ 64
#define BKT 32
__global__ __launch_bounds__(256)
void attn_kernel(const float* __restrict__ qkv,
                 __nv_bfloat16* __restrict__ chi, __nv_bfloat16* __restrict__ clo) {
    __shared__ float Qs[BQ][DHH + 1];
    __shared__ float Ks[BKT][DHH + 2];
    __shared__ float Vs[BKT][DHH + 2];
    __shared__ float Ss[BQ][BKT + 2];
    __shared__ float m_sh[BQ], l_sh[BQ], al_sh[BQ];

    const int t  = threadIdx.x;
    const int tx = t & 15;
    const int ty = t >> 4;
    const int b  = blockIdx.y >> 4;
    const int h  = blockIdx.y & 15;
    const int q0 = blockIdx.x * BQ;
    const int hd = h * DHH;

#pragma unroll
    for (int p = 0; p < (BQ * DHH) / 256; ++p) {
        int idx = t + p * 256;
        int r = idx >> 6, d = idx & 63;
        Qs[r][d] = qkv[((size_t)((q0 + r) * BBB + b)) * 3072 + hd + d] * 0.125f;
    }
    if (t < BQ) { m_sh[t] = -1e30f; l_sh[t] = 0.f; }

    float O[4][4];
#pragma unroll
    for (int i = 0; i < 4; i++)
#pragma unroll
        for (int j = 0; j < 4; j++) O[i][j] = 0.f;
    __syncthreads();

    for (int kt = 0; kt < SSS / BKT; ++kt) {
#pragma unroll
        for (int p = 0; p < (BKT * DHH) / 256; ++p) {
            int idx = t + p * 256;
            int r = idx >> 6, d = idx & 63;
            size_t base = ((size_t)((kt * BKT + r) * BBB + b)) * 3072 + hd + d;
            Ks[r][d] = qkv[base + 1024];
            Vs[r][d] = qkv[base + 2048];
        }
        __syncthreads();

        float sacc[4][2] = {{0.f, 0.f}, {0.f, 0.f}, {0.f, 0.f}, {0.f, 0.f}};
#pragma unroll
        for (int d = 0; d < DHH; ++d) {
            float k0v = Ks[tx * 2 + 0][d];
            float k1v = Ks[tx * 2 + 1][d];
#pragma unroll
            for (int i = 0; i < 4; i++) {
                float qv = Qs[ty * 4 + i][d];
                sacc[i][0] += qv * k0v;
                sacc[i][1] += qv * k1v;
            }
        }
#pragma unroll
        for (int i = 0; i < 4; i++) {
            Ss[ty * 4 + i][tx * 2 + 0] = sacc[i][0];
            Ss[ty * 4 + i][tx * 2 + 1] = sacc[i][1];
        }
        __syncthreads();

        if (t < BQ) {
            float mprev = m_sh[t];
            float mx = mprev;
            for (int j = 0; j < BKT; j++) mx = fmaxf(mx, Ss[t][j]);
            float al = expf(mprev - mx);
            float sum = 0.f;
            for (int j = 0; j < BKT; j++) {
                float p = expf(Ss[t][j] - mx);
                Ss[t][j] = p;
                sum += p;
            }
            m_sh[t]  = mx;
            l_sh[t]  = l_sh[t] * al + sum;
            al_sh[t] = al;
        }
        __syncthreads();

#pragma unroll
        for (int i = 0; i < 4; i++) {
            float al = al_sh[ty * 4 + i];
            float pv[4] = {0.f, 0.f, 0.f, 0.f};
            for (int k = 0; k < BKT; k++) {
                float p = Ss[ty * 4 + i][k];
#pragma unroll
                for (int j = 0; j < 4; j++) pv[j] += p * Vs[k][tx * 4 + j];
            }
#pragma unroll
            for (int j = 0; j < 4; j++) O[i][j] = O[i][j] * al + pv[j];
        }
        __syncthreads();
    }

#pragma unroll
    for (int i = 0; i < 4; i++) {
        int r = ty * 4 + i;
        float invl = 1.f / l_sh[r];
#pragma unroll
        for (int j = 0; j < 4; j++) {
            float o = O[i][j] * invl;
            size_t oi = ((size_t)((q0 + r) * BBB + b)) * 1024 + hd + tx * 4 + j;
            __nv_bfloat16 hh, ll;
            split_bf16(o, hh, ll);
            chi[oi] = hh; clo[oi] = ll;
        }
    }
}

// ---------------------------------------------------------------------------
// 4) LayerNorm: out = LN(a [+ r]) * g + b  (+ bf16 split emit)
// ---------------------------------------------------------------------------
__global__ __launch_bounds__(256)
void ln_kernel(const float* __restrict__ a, const float* __restrict__ r,
               const float* __restrict__ g, const float* __restrict__ b,
               float* __restrict__ out,
               __nv_bfloat16* __restrict__ ohi, __nv_bfloat16* __restrict__ olo) {
    __shared__ float red[256];
    const int t = threadIdx.x;
    const size_t row = blockIdx.x;
    float4 v = reinterpret_cast<const float4*>(a + row * 1024)[t];
    if (r != nullptr) {
        float4 rv = reinterpret_cast<const float4*>(r + row * 1024)[t];
        v.x += rv.x; v.y += rv.y; v.z += rv.z; v.w += rv.w;
    }
    red[t] = v.x + v.y + v.z + v.w;
    __syncthreads();
    for (int o = 128; o > 0; o >>= 1) {
        if (t < o) red[t] += red[t + o];
        __syncthreads();
    }
    float mu = red[0] * (1.f / 1024.f);
    __syncthreads();
    float dx = v.x - mu, dy = v.y - mu, dz = v.z - mu, dw = v.w - mu;
    red[t] = dx * dx + dy * dy + dz * dz + dw * dw;
    __syncthreads();
    for (int o = 128; o > 0; o >>= 1) {
        if (t < o) red[t] += red[t + o];
        __syncthreads();
    }
    float inv = rsqrtf(red[0] * (1.f / 1024.f) + 1e-5f);
    float4 g4 = reinterpret_cast<const float4*>(g)[t];
    float4 b4 = reinterpret_cast<const float4*>(b)[t];
    float4 o4;
    o4.x = dx * inv * g4.x + b4.x;
    o4.y = dy * inv * g4.y + b4.y;
    o4.z = dz * inv * g4.z + b4.z;
    o4.w = dw * inv * g4.w + b4.w;
    reinterpret_cast<float4*>(out + row * 1024)[t] = o4;
    if (ohi != nullptr) {
        __nv_bfloat16 h0, h1, h2, h3, l0, l1, l2, l3;
        split_bf16(o4.x, h0, l0); split_bf16(o4.y, h1, l1);
        split_bf16(o4.z, h2, l2); split_bf16(o4.w, h3, l3);
        __nv_bfloat162 p0, p1;
        p0.x = h0; p0.y = h1; p1.x = h2; p1.y = h3;
        reinterpret_cast<__nv_bfloat162*>(ohi + row * 1024)[2 * t]     = p0;
        reinterpret_cast<__nv_bfloat162*>(ohi + row * 1024)[2 * t + 1] = p1;
        p0.x = l0; p0.y = l1; p1.x = l2; p1.y = l3;
        reinterpret_cast<__nv_bfloat162*>(olo + row * 1024)[2 * t]     = p0;
        reinterpret_cast<__nv_bfloat162*>(olo + row * 1024)[2 * t + 1] = p1;
    }
}

// ---------------------------------------------------------------------------
// Host orchestration (graph-capturable: kernel launches only)
// ---------------------------------------------------------------------------
extern "C" void kernel_launch(void* const* d_in, const int* in_sizes, int n_in,
                              void* d_out, int out_size) {
    (void)in_sizes; (void)n_in; (void)out_size;
    const float* x    = (const float*)d_in[0];
    const float* Wqkv = (const float*)d_in[1];
    const float* bqkv = (const float*)d_in[2];
    const float* Wo   = (const float*)d_in[3];
    const float* bo   = (const float*)d_in[4];
    const float* W1   = (const float*)d_in[5];
    const float* b1   = (const float*)d_in[6];
    const float* W2   = (const float*)d_in[7];
    const float* b2   = (const float*)d_in[8];
    const float* ln1g = (const float*)d_in[9];
    const float* ln1b = (const float*)d_in[10];
    const float* ln2g = (const float*)d_in[11];
    const float* ln2b = (const float*)d_in[12];
    const float* lnfg = (const float*)d_in[13];
    const float* lnfb = (const float*)d_in[14];
    const float* Wout = (const float*)d_in[15];
    const float* bout = (const float*)d_in[16];
    float* out = (float*)d_out;

    float *h, *qkv, *tmp;
    __nv_bfloat16 *hhi, *hlo, *bhi, *blo, *whi, *wlo;
    cudaGetSymbolAddress((void**)&h,   g_h);
    cudaGetSymbolAddress((void**)&qkv, g_qkv);
    cudaGetSymbolAddress((void**)&tmp, g_tmp);
    cudaGetSymbolAddress((void**)&hhi, g_hhi);
    cudaGetSymbolAddress((void**)&hlo, g_hlo);
    cudaGetSymbolAddress((void**)&bhi, g_bhi);
    cudaGetSymbolAddress((void**)&blo, g_blo);
    cudaGetSymbolAddress((void**)&whi, g_whi);
    cudaGetSymbolAddress((void**)&wlo, g_wlo);

    cudaFuncSetAttribute(gemm_mma<0, 0, 0>, cudaFuncAttributeMaxDynamicSharedMemorySize, GEMM_SMEM);
    cudaFuncSetAttribute(gemm_mma<1, 0, 1>, cudaFuncAttributeMaxDynamicSharedMemorySize, GEMM_SMEM);
    cudaFuncSetAttribute(gemm_mma<0, 1, 0>, cudaFuncAttributeMaxDynamicSharedMemorySize, GEMM_SMEM);

    // weight splits
    cvt_split_kernel<<<12288, 256>>>(Wqkv, whi + OFF_QKV, wlo + OFF_QKV, 3145728);
    cvt_split_kernel<<<4096, 256>>>(Wo,   whi + OFF_WO,   wlo + OFF_WO,  1048576);
    cvt_split_kernel<<<8192, 256>>>(W1,   whi + OFF_W1,   wlo + OFF_W1,  2097152);
    cvt_split_kernel<<<8192, 256>>>(W2,   whi + OFF_W2,   wlo + OFF_W2,  2097152);
    cvt_split_kernel<<<512, 256>>>(Wout,  whi + OFF_WOUT, wlo + OFF_WOUT, 131072);

    add_pe_kernel<<<(TTT * DDD) / 256, 256>>>(x, h, hhi, hlo);

    for (int l = 0; l < LLL; l++) {
        const __nv_bfloat16* wq_h = whi + OFF_QKV + (size_t)l * 3145728;
        const __nv_bfloat16* wq_l = wlo + OFF_QKV + (size_t)l * 3145728;
        const __nv_bfloat16* wo_h = whi + OFF_WO + (size_t)l * 1048576;
        const __nv_bfloat16* wo_l = wlo + OFF_WO + (size_t)l * 1048576;
        const __nv_bfloat16* w1_h = whi + OFF_W1 + (size_t)l * 2097152;
        const __nv_bfloat16* w1_l = wlo + OFF_W1 + (size_t)l * 2097152;
        const __nv_bfloat16* w2_h = whi + OFF_W2 + (size_t)l * 2097152;
        const __nv_bfloat16* w2_l = wlo + OFF_W2 + (size_t)l * 2097152;

        // qkv = h @ Wqkv^T + bqkv
        gemm_mma<0, 0, 0><<<dim3(3072 / 128, TTT / 128), 256, GEMM_SMEM>>>(
            hhi, hlo, wq_h, wq_l, bqkv + (size_t)l * 3072, qkv, nullptr, nullptr,
            TTT, 3072, 1024);
        // ctx (bf16 split) = attention
        attn_kernel<<<dim3(SSS / BQ, BBB * HHH), 256>>>(qkv, bhi, blo);
        // tmp = ctx @ Wo^T + bo
        gemm_mma<0, 0, 0><<<dim3(1024 / 128, TTT / 128), 256, GEMM_SMEM>>>(
            bhi, blo, wo_h, wo_l, bo + (size_t)l * 1024, tmp, nullptr, nullptr,
            TTT, 1024, 1024);
        // h = LN(h + tmp), emit split
        ln_kernel<<<TTT, 256>>>(h, tmp, ln1g + (size_t)l * 1024, ln1b + (size_t)l * 1024,
                                h, hhi, hlo);
        // ff (bf16 split) = relu(h @ W1^T + b1)
        gemm_mma<1, 0, 1><<<dim3(2048 / 128, TTT / 128), 256, GEMM_SMEM>>>(
            hhi, hlo, w1_h, w1_l, b1 + (size_t)l * 2048, nullptr, bhi, blo,
            TTT, 2048, 1024);
        // tmp = ff @ W2^T + b2
        gemm_mma<0, 0, 0><<<dim3(1024 / 128, TTT / 128), 256, GEMM_SMEM>>>(
            bhi, blo, w2_h, w2_l, b2 + (size_t)l * 1024, tmp, nullptr, nullptr,
            TTT, 1024, 2048);
        // h = LN(h + ff2), emit split
        ln_kernel<<<TTT, 256>>>(h, tmp, ln2g + (size_t)l * 1024, ln2b + (size_t)l * 1024,
                                h, hhi, hlo);
    }

    // final norm (emit split for the output GEMM)
    ln_kernel<<<TTT, 256>>>(h, nullptr, lnfg, lnfb, h, hhi, hlo);
    // out[b,s,:] = h_final[s,b,:] @ Wout^T + bout (PERM fuses transpose)
    gemm_mma<0, 1, 0><<<dim3(DMEMM / 128, TTT / 128), 256, GEMM_SMEM>>>(
        hhi, hlo, whi + OFF_WOUT, wlo + OFF_WOUT, bout, out, nullptr, nullptr,
        TTT, DMEMM, 1024);
}

// round 4
// speedup vs baseline: 2.7040x; 1.5445x over previous
#include <cuda_runtime.h>
#include <cuda_bf16.h>
#include <math.h>
#include <stdint.h>

// Problem constants
#define BBB 32
#define SSS 512
#define DDD 1024
#define HHH 16
#define DHH 64
#define LLL 4
#define DFFF 2048
#define DMEMM 512
#define TTT (BBB * SSS)   // 16384 tokens

// ---------------------------------------------------------------------------
// Scratch (static device globals — no allocation at runtime)
// ---------------------------------------------------------------------------
__device__ float g_h[(size_t)TTT * DDD];              //  64 MB
__device__ float g_tmp[(size_t)TTT * DDD];            //  64 MB
__device__ __nv_bfloat16 g_hhi[(size_t)TTT * DDD];    //  32 MB
__device__ __nv_bfloat16 g_hlo[(size_t)TTT * DDD];
__device__ __nv_bfloat16 g_bhi[(size_t)TTT * DFFF];   //  64 MB  ctx / ff split
__device__ __nv_bfloat16 g_blo[(size_t)TTT * DFFF];
__device__ __nv_bfloat16 g_qkvhi[(size_t)TTT * 3 * DDD];  // 96 MB
__device__ __nv_bfloat16 g_qkvlo[(size_t)TTT * 3 * DDD];  // 96 MB
#define WTOT 34078720ULL
__device__ __nv_bfloat16 g_whi[WTOT];
__device__ __nv_bfloat16 g_wlo[WTOT];

#define OFF_QKV 0ULL
#define OFF_WO  12582912ULL
#define OFF_W1  16777216ULL
#define OFF_W2  25165824ULL
#define OFF_WOUT 33554432ULL

// ---------------------------------------------------------------------------
// PTX helpers (baseline sm_80+: mma.sync / ldmatrix / cp.async)
// ---------------------------------------------------------------------------
__device__ __forceinline__ uint32_t smem_u32(const void* p) {
    uint32_t a;
    asm("{ .reg .u64 t; cvta.to.shared.u64 t, %1; cvt.u32.u64 %0, t; }" : "=r"(a) : "l"(p));
    return a;
}

#define CP16(saddr, gptr) \
    asm volatile("cp.async.cg.shared.global [%0], [%1], 16;" :: "r"(saddr), "l"(gptr))
#define CPCOMMIT() asm volatile("cp.async.commit_group;" ::: "memory")
#define CPWAIT(n)  asm volatile("cp.async.wait_group %0;" :: "n"(n) : "memory")

#define LDSM4(r, addr)                                                          \
    asm volatile("ldmatrix.sync.aligned.m8n8.x4.shared.b16 {%0,%1,%2,%3}, [%4];" \
        : "=r"((r)[0]), "=r"((r)[1]), "=r"((r)[2]), "=r"((r)[3]) : "r"(addr))

#define LDSM4T(r, addr)                                                          \
    asm volatile("ldmatrix.sync.aligned.m8n8.x4.trans.shared.b16 {%0,%1,%2,%3}, [%4];" \
        : "=r"((r)[0]), "=r"((r)[1]), "=r"((r)[2]), "=r"((r)[3]) : "r"(addr))

#define MMA_BF16(d, a, b0v, b1v)                                                \
    asm volatile("mma.sync.aligned.m16n8k16.row.col.f32.bf16.bf16.f32 "         \
        "{%0,%1,%2,%3}, {%4,%5,%6,%7}, {%8,%9}, {%0,%1,%2,%3};"                 \
        : "+f"((d)[0]), "+f"((d)[1]), "+f"((d)[2]), "+f"((d)[3])                \
        : "r"((a)[0]), "r"((a)[1]), "r"((a)[2]), "r"((a)[3]), "r"(b0v), "r"(b1v))

__device__ __forceinline__ void split_bf16(float v, __nv_bfloat16& h, __nv_bfloat16& l) {
    h = __float2bfloat16(v);
    l = __float2bfloat16(v - __bfloat162float(h));
}
// pack (lo=a, hi=b) into bf16x2
__device__ __forceinline__ uint32_t pack_hi2(float a, float b) {
    uint32_t r;
    asm("cvt.rn.bf16x2.f32 %0, %1, %2;" : "=r"(r) : "f"(b), "f"(a));
    return r;
}
__device__ __forceinline__ float bf_round(float v) {
    return __bfloat162float(__float2bfloat16(v));
}

// ---------------------------------------------------------------------------
// 0) weight split
// ---------------------------------------------------------------------------
__global__ __launch_bounds__(256)
void cvt_split_kernel(const float* __restrict__ in, __nv_bfloat16* __restrict__ hi,
                      __nv_bfloat16* __restrict__ lo, int n4) {
    int i = blockIdx.x * 256 + threadIdx.x;
    if (i >= n4) return;
    float4 v = reinterpret_cast<const float4*>(in)[i];
    __nv_bfloat16 h0, h1, h2, h3, l0, l1, l2, l3;
    split_bf16(v.x, h0, l0); split_bf16(v.y, h1, l1);
    split_bf16(v.z, h2, l2); split_bf16(v.w, h3, l3);
    __nv_bfloat162 a, b;
    a.x = h0; a.y = h1; b.x = h2; b.y = h3;
    reinterpret_cast<__nv_bfloat162*>(hi)[2 * i]     = a;
    reinterpret_cast<__nv_bfloat162*>(hi)[2 * i + 1] = b;
    a.x = l0; a.y = l1; b.x = l2; b.y = l3;
    reinterpret_cast<__nv_bfloat162*>(lo)[2 * i]     = a;
    reinterpret_cast<__nv_bfloat162*>(lo)[2 * i + 1] = b;
}

// ---------------------------------------------------------------------------
// 1) h[s,b,:] = x[b,s,:] + PE(s,:)   (+ split emit)
// ---------------------------------------------------------------------------
__global__ __launch_bounds__(256)
void add_pe_kernel(const float* __restrict__ x, float* __restrict__ h,
                   __nv_bfloat16* __restrict__ hhi, __nv_bfloat16* __restrict__ hlo) {
    int idx = blockIdx.x * blockDim.x + threadIdx.x;
    int d   = idx & (DDD - 1);
    int row = idx >> 10;
    int s   = row >> 5;
    int b   = row & 31;
    float div = expf((float)(d & ~1) * (-9.2103403719761836f / (float)DDD));
    float ang = (float)s * div;
    float pe  = (d & 1) ? cosf(ang) : sinf(ang);
    float v = x[((size_t)(b * SSS + s) << 10) + d] + pe;
    h[idx] = v;
    __nv_bfloat16 hh, ll;
    split_bf16(v, hh, ll);
    hhi[idx] = hh; hlo[idx] = ll;
}

// ---------------------------------------------------------------------------
// 2) HMMA GEMM (bf16x3), unchanged from round 3
// ---------------------------------------------------------------------------
#define SROWB 80
#define A_HI 0u
#define A_LO 10240u
#define W_HI 20480u
#define W_LO 30720u
#define STAGE_B 40960u
#define GEMM_SMEM (2 * 40960)

template <int PERM>
__device__ __forceinline__ void load_stage(
    uint32_t sbase,
    const __nv_bfloat16* __restrict__ Ahi, const __nv_bfloat16* __restrict__ Alo,
    const __nv_bfloat16* __restrict__ Whi, const __nv_bfloat16* __restrict__ Wlo,
    int m0, int n0, int K, int k0, int t) {
#pragma unroll
    for (int i = 0; i < 2; ++i) {
        int u = t + i * 256;
        int row = u >> 2, c8 = u & 3;
        int garow = m0 + row;
        if (PERM) garow = ((garow & 511) << 5) | (garow >> 9);
        const __nv_bfloat16* pa_hi = Ahi + (size_t)garow * K + k0 + c8 * 8;
        const __nv_bfloat16* pa_lo = Alo + (size_t)garow * K + k0 + c8 * 8;
        const __nv_bfloat16* pw_hi = Whi + (size_t)(n0 + row) * K + k0 + c8 * 8;
        const __nv_bfloat16* pw_lo = Wlo + (size_t)(n0 + row) * K + k0 + c8 * 8;
        uint32_t d = (uint32_t)(row * SROWB + c8 * 16);
        CP16(sbase + A_HI + d, pa_hi);
        CP16(sbase + A_LO + d, pa_lo);
        CP16(sbase + W_HI + d, pw_hi);
        CP16(sbase + W_LO + d, pw_lo);
    }
}

template <int RELU, int PERM, int SPLIT>
__global__ __launch_bounds__(256)
void gemm_mma(const __nv_bfloat16* __restrict__ Ahi, const __nv_bfloat16* __restrict__ Alo,
              const __nv_bfloat16* __restrict__ Whi, const __nv_bfloat16* __restrict__ Wlo,
              const float* __restrict__ bias, float* __restrict__ C,
              __nv_bfloat16* __restrict__ Chi, __nv_bfloat16* __restrict__ Clo,
              int M, int N, int K) {
    extern __shared__ char smem[];
    const uint32_t sb = smem_u32(smem);
    const int t    = threadIdx.x;
    const int lane = t & 31;
    const int w    = t >> 5;
    const int wm   = w & 1;
    const int wn   = w >> 1;
    const int m0   = blockIdx.y * 128;
    const int n0   = blockIdx.x * 128;

    float acc[4][4][4];
#pragma unroll
    for (int a = 0; a < 4; a++)
#pragma unroll
        for (int b = 0; b < 4; b++)
#pragma unroll
            for (int c = 0; c < 4; c++) acc[a][b][c] = 0.f;

    const uint32_t a_off = (uint32_t)((wm * 64 + (lane & 15)) * SROWB + (lane >> 4) * 16);
    const int brow = wn * 32 + (lane & 7) + ((lane & 16) >> 1);
    const uint32_t b_off = (uint32_t)(brow * SROWB + ((lane >> 3) & 1) * 16);

    const int NC = K >> 5;
    load_stage<PERM>(sb, Ahi, Alo, Whi, Wlo, m0, n0, K, 0, t);
    CPCOMMIT();

    for (int c = 0; c < NC; ++c) {
        const uint32_t stb = sb + (uint32_t)(c & 1) * STAGE_B;
        if (c + 1 < NC) {
            load_stage<PERM>(sb + (uint32_t)((c + 1) & 1) * STAGE_B,
                             Ahi, Alo, Whi, Wlo, m0, n0, K, (c + 1) << 5, t);
            CPCOMMIT();
            CPWAIT(1);
        } else {
            CPWAIT(0);
        }
        __syncthreads();
#pragma unroll
        for (int ks = 0; ks < 2; ++ks) {
            const uint32_t ao = stb + a_off + ks * 32;
            const uint32_t bo = stb + b_off + ks * 32;
            uint32_t fa_hi[4][4], fa_lo[4][4];
#pragma unroll
            for (int mi = 0; mi < 4; ++mi) {
                LDSM4(fa_hi[mi], ao + A_HI + mi * (16 * SROWB));
                LDSM4(fa_lo[mi], ao + A_LO + mi * (16 * SROWB));
            }
            uint32_t fb_hi[2][4], fb_lo[2][4];
#pragma unroll
            for (int nj = 0; nj < 2; ++nj) {
                LDSM4(fb_hi[nj], bo + W_HI + nj * (16 * SROWB));
                LDSM4(fb_lo[nj], bo + W_LO + nj * (16 * SROWB));
            }
#pragma unroll
            for (int mi = 0; mi < 4; ++mi)
#pragma unroll
                for (int ni = 0; ni < 4; ++ni) {
                    const int nj = ni >> 1, kk = (ni & 1) * 2;
                    MMA_BF16(acc[mi][ni], fa_hi[mi], fb_hi[nj][kk], fb_hi[nj][kk + 1]);
                    MMA_BF16(acc[mi][ni], fa_hi[mi], fb_lo[nj][kk], fb_lo[nj][kk + 1]);
                    MMA_BF16(acc[mi][ni], fa_lo[mi], fb_hi[nj][kk], fb_hi[nj][kk + 1]);
                }
        }
        __syncthreads();
    }

    const int qrow = lane >> 2;
    const int qcol = (lane & 3) * 2;
#pragma unroll
    for (int mi = 0; mi < 4; ++mi) {
        const int row0 = m0 + wm * 64 + mi * 16 + qrow;
#pragma unroll
        for (int ni = 0; ni < 4; ++ni) {
            const int col = n0 + wn * 32 + ni * 8 + qcol;
            const float bb0 = bias[col];
            const float bb1 = bias[col + 1];
            float v00 = acc[mi][ni][0] + bb0;
            float v01 = acc[mi][ni][1] + bb1;
            float v10 = acc[mi][ni][2] + bb0;
            float v11 = acc[mi][ni][3] + bb1;
            if (RELU) {
                v00 = fmaxf(v00, 0.f); v01 = fmaxf(v01, 0.f);
                v10 = fmaxf(v10, 0.f); v11 = fmaxf(v11, 0.f);
            }
            if (SPLIT) {
                __nv_bfloat16 h0, l0, h1, l1;
                __nv_bfloat162 hh, ll;
                split_bf16(v00, h0, l0); split_bf16(v01, h1, l1);
                hh.x = h0; hh.y = h1; ll.x = l0; ll.y = l1;
                *reinterpret_cast<__nv_bfloat162*>(Chi + (size_t)row0 * N + col) = hh;
                *reinterpret_cast<__nv_bfloat162*>(Clo + (size_t)row0 * N + col) = ll;
                split_bf16(v10, h0, l0); split_bf16(v11, h1, l1);
                hh.x = h0; hh.y = h1; ll.x = l0; ll.y = l1;
                *reinterpret_cast<__nv_bfloat162*>(Chi + (size_t)(row0 + 8) * N + col) = hh;
                *reinterpret_cast<__nv_bfloat162*>(Clo + (size_t)(row0 + 8) * N + col) = ll;
            } else {
                *reinterpret_cast<float2*>(C + (size_t)row0 * N + col) =
                    make_float2(v00, v01);
                *reinterpret_cast<float2*>(C + (size_t)(row0 + 8) * N + col) =
                    make_float2(v10, v11);
            }
        }
    }
}

// ---------------------------------------------------------------------------
// 3) HMMA flash attention, bf16x3 compensated
// ---------------------------------------------------------------------------
#define AROWB 144
#define AQ_HI 0u
#define AQ_LO 18432u
#define AST0  36864u
#define ASTG  36864u
#define AK_HI 0u
#define AK_LO 9216u
#define AV_HI 18432u
#define AV_LO 27648u
#define ATTN_SMEM (36864 + 2 * 36864)

__device__ __forceinline__ void attn_load_kv(
    uint32_t sbase, const __nv_bfloat16* __restrict__ qhi,
    const __nv_bfloat16* __restrict__ qlo, int b, int hd, int kt, int t) {
#pragma unroll
    for (int i = 0; i < 8; ++i) {
        int u = t + i * 256;             // 0..2047
        int sel = u >> 9;                // 0 Khi, 1 Klo, 2 Vhi, 3 Vlo
        int v = u & 511;
        int row = v >> 3, seg = v & 7;
        const __nv_bfloat16* base = (sel & 1) ? qlo : qhi;
        int off = (sel >> 1) ? 2048 : 1024;
        const __nv_bfloat16* src =
            base + ((size_t)((kt * 64 + row) * BBB + b)) * 3072 + off + hd + seg * 8;
        uint32_t dst = sbase + (uint32_t)sel * 9216u + (uint32_t)(row * AROWB + seg * 16);
        CP16(dst, src);
    }
}

__global__ __launch_bounds__(256, 2)
void attn_mma_kernel(const __nv_bfloat16* __restrict__ qhi,
                     const __nv_bfloat16* __restrict__ qlo,
                     __nv_bfloat16* __restrict__ chi, __nv_bfloat16* __restrict__ clo) {
    extern __shared__ char smem[];
    const uint32_t sb = smem_u32(smem);
    const int t    = threadIdx.x;
    const int lane = t & 31;
    const int w    = t >> 5;
    const int b    = blockIdx.y >> 4;
    const int h    = blockIdx.y & 15;
    const int q0   = blockIdx.x * 128;
    const int hd   = h * DHH;

    // load Q hi/lo (128 x 64)
#pragma unroll
    for (int i = 0; i < 8; ++i) {
        int u = t + i * 256;
        int ishi = (u < 1024);
        int v = u & 1023;
        int row = v >> 3, seg = v & 7;
        const __nv_bfloat16* src = (ishi ? qhi : qlo) +
            ((size_t)((q0 + row) * BBB + b)) * 3072 + hd + seg * 8;
        uint32_t dst = sb + (ishi ? AQ_HI : AQ_LO) + (uint32_t)(row * AROWB + seg * 16);
        CP16(dst, src);
    }
    CPCOMMIT();
    attn_load_kv(sb + AST0, qhi, qlo, b, hd, 0, t);
    CPCOMMIT();

    float Oa[8][4];
#pragma unroll
    for (int j = 0; j < 8; j++)
#pragma unroll
        for (int c = 0; c < 4; c++) Oa[j][c] = 0.f;
    float m0r = -1e30f, m1r = -1e30f, l0r = 0.f, l1r = 0.f;

    const uint32_t arow_off = (uint32_t)((w * 16 + (lane & 15)) * AROWB + (lane >> 4) * 16);
    const uint32_t brow_off = (uint32_t)(((lane & 7) + ((lane & 16) >> 1)) * AROWB +
                                         ((lane >> 3) & 1) * 16);
    const uint32_t vrow_off = (uint32_t)((lane & 15) * AROWB + (lane >> 4) * 16);

    for (int kt = 0; kt < 8; ++kt) {
        CPWAIT(0);
        __syncthreads();
        if (kt + 1 < 8) {
            attn_load_kv(sb + AST0 + (uint32_t)((kt + 1) & 1) * ASTG, qhi, qlo, b, hd,
                         kt + 1, t);
            CPCOMMIT();
        }
        const uint32_t stg = sb + AST0 + (uint32_t)(kt & 1) * ASTG;

        // ---- S = Q K^T (3-pass split), fp32 acc ----
        float st[8][4];
#pragma unroll
        for (int j = 0; j < 8; j++)
#pragma unroll
            for (int c = 0; c < 4; c++) st[j][c] = 0.f;
#pragma unroll
        for (int pass = 0; pass < 3; ++pass) {
            const uint32_t abase = sb + (pass == 2 ? AQ_LO : AQ_HI) + arow_off;
            const uint32_t bbase = stg + (pass == 1 ? AK_LO : AK_HI) + brow_off;
#pragma unroll
            for (int kc = 0; kc < 4; ++kc) {
                uint32_t fa[4];
                LDSM4(fa, abase + kc * 32);
#pragma unroll
                for (int g = 0; g < 4; ++g) {
                    uint32_t fb[4];
                    LDSM4(fb, bbase + g * (16 * AROWB) + kc * 32);
                    MMA_BF16(st[2 * g],     fa, fb[0], fb[1]);
                    MMA_BF16(st[2 * g + 1], fa, fb[2], fb[3]);
                }
            }
        }

        // ---- online softmax ----
        float mx0 = -1e30f, mx1 = -1e30f;
#pragma unroll
        for (int j = 0; j < 8; j++) {
            st[j][0] *= 0.125f; st[j][1] *= 0.125f;
            st[j][2] *= 0.125f; st[j][3] *= 0.125f;
            mx0 = fmaxf(mx0, fmaxf(st[j][0], st[j][1]));
            mx1 = fmaxf(mx1, fmaxf(st[j][2], st[j][3]));
        }
        mx0 = fmaxf(mx0, __shfl_xor_sync(0xffffffffu, mx0, 1));
        mx0 = fmaxf(mx0, __shfl_xor_sync(0xffffffffu, mx0, 2));
        mx1 = fmaxf(mx1, __shfl_xor_sync(0xffffffffu, mx1, 1));
        mx1 = fmaxf(mx1, __shfl_xor_sync(0xffffffffu, mx1, 2));
        const float nm0 = fmaxf(m0r, mx0), nm1 = fmaxf(m1r, mx1);
        const float al0 = __expf(m0r - nm0), al1 = __expf(m1r - nm1);
        float s0 = 0.f, s1 = 0.f;
#pragma unroll
        for (int j = 0; j < 8; j++) {
            st[j][0] = __expf(st[j][0] - nm0);
            st[j][1] = __expf(st[j][1] - nm0);
            st[j][2] = __expf(st[j][2] - nm1);
            st[j][3] = __expf(st[j][3] - nm1);
            s0 += st[j][0] + st[j][1];
            s1 += st[j][2] + st[j][3];
        }
        s0 += __shfl_xor_sync(0xffffffffu, s0, 1);
        s0 += __shfl_xor_sync(0xffffffffu, s0, 2);
        s1 += __shfl_xor_sync(0xffffffffu, s1, 1);
        s1 += __shfl_xor_sync(0xffffffffu, s1, 2);
        l0r = l0r * al0 + s0;
        l1r = l1r * al1 + s1;
        m0r = nm0; m1r = nm1;
#pragma unroll
        for (int j = 0; j < 8; j++) {
            Oa[j][0] *= al0; Oa[j][1] *= al0;
            Oa[j][2] *= al1; Oa[j][3] *= al1;
        }

        // ---- O += P V (3-pass split); V via ldmatrix.trans ----
#pragma unroll
        for (int kc = 0; kc < 4; ++kc) {
            uint32_t ah[4], alo[4];
            {
                const float* p0 = st[2 * kc];
                const float* p1 = st[2 * kc + 1];
                ah[0] = pack_hi2(p0[0], p0[1]);
                ah[1] = pack_hi2(p0[2], p0[3]);
                ah[2] = pack_hi2(p1[0], p1[1]);
                ah[3] = pack_hi2(p1[2], p1[3]);
                alo[0] = pack_hi2(p0[0] - bf_round(p0[0]), p0[1] - bf_round(p0[1]));
                alo[1] = pack_hi2(p0[2] - bf_round(p0[2]), p0[3] - bf_round(p0[3]));
                alo[2] = pack_hi2(p1[0] - bf_round(p1[0]), p1[1] - bf_round(p1[1]));
                alo[3] = pack_hi2(p1[2] - bf_round(p1[2]), p1[3] - bf_round(p1[3]));
            }
            const uint32_t vbase = stg + (uint32_t)(kc * 16 * AROWB) + vrow_off;
#pragma unroll
            for (int g = 0; g < 4; ++g) {
                uint32_t fvh[4], fvl[4];
                LDSM4T(fvh, vbase + AV_HI + g * 32);
                MMA_BF16(Oa[2 * g],     ah,  fvh[0], fvh[1]);
                MMA_BF16(Oa[2 * g + 1], ah,  fvh[2], fvh[3]);
                MMA_BF16(Oa[2 * g],     alo, fvh[0], fvh[1]);
                MMA_BF16(Oa[2 * g + 1], alo, fvh[2], fvh[3]);
                LDSM4T(fvl, vbase + AV_LO + g * 32);
                MMA_BF16(Oa[2 * g],     ah,  fvl[0], fvl[1]);
                MMA_BF16(Oa[2 * g + 1], ah,  fvl[2], fvl[3]);
            }
        }
    }

    // ---- epilogue ----
    const float inv0 = 1.f / l0r;
    const float inv1 = 1.f / l1r;
    const int r_lo = q0 + w * 16 + (lane >> 2);
    const int col0 = hd + (lane & 3) * 2;
#pragma unroll
    for (int j = 0; j < 8; j++) {
        const int col = col0 + j * 8;
        float v0 = Oa[j][0] * inv0, v1 = Oa[j][1] * inv0;
        float v2 = Oa[j][2] * inv1, v3 = Oa[j][3] * inv1;
        __nv_bfloat16 h0, l0, h1, l1;
        __nv_bfloat162 hh, ll;
        size_t o0 = ((size_t)(r_lo * BBB + b)) * 1024 + col;
        split_bf16(v0, h0, l0); split_bf16(v1, h1, l1);
        hh.x = h0; hh.y = h1; ll.x = l0; ll.y = l1;
        *reinterpret_cast<__nv_bfloat162*>(chi + o0) = hh;
        *reinterpret_cast<__nv_bfloat162*>(clo + o0) = ll;
        size_t o1 = ((size_t)((r_lo + 8) * BBB + b)) * 1024 + col;
        split_bf16(v2, h0, l0); split_bf16(v3, h1, l1);
        hh.x = h0; hh.y = h1; ll.x = l0; ll.y = l1;
        *reinterpret_cast<__nv_bfloat162*>(chi + o1) = hh;
        *reinterpret_cast<__nv_bfloat162*>(clo + o1) = ll;
    }
}

// ---------------------------------------------------------------------------
// 4) LayerNorm (+ bf16 split emit)
// ---------------------------------------------------------------------------
__global__ __launch_bounds__(256)
void ln_kernel(const float* __restrict__ a, const float* __restrict__ r,
               const float* __restrict__ g, const float* __restrict__ b,
               float* __restrict__ out,
               __nv_bfloat16* __restrict__ ohi, __nv_bfloat16* __restrict__ olo) {
    __shared__ float red[256];
    const int t = threadIdx.x;
    const size_t row = blockIdx.x;
    float4 v = reinterpret_cast<const float4*>(a + row * 1024)[t];
    if (r != nullptr) {
        float4 rv = reinterpret_cast<const float4*>(r + row * 1024)[t];
        v.x += rv.x; v.y += rv.y; v.z += rv.z; v.w += rv.w;
    }
    red[t] = v.x + v.y + v.z + v.w;
    __syncthreads();
    for (int o = 128; o > 0; o >>= 1) {
        if (t < o) red[t] += red[t + o];
        __syncthreads();
    }
    float mu = red[0] * (1.f / 1024.f);
    __syncthreads();
    float dx = v.x - mu, dy = v.y - mu, dz = v.z - mu, dw = v.w - mu;
    red[t] = dx * dx + dy * dy + dz * dz + dw * dw;
    __syncthreads();
    for (int o = 128; o > 0; o >>= 1) {
        if (t < o) red[t] += red[t + o];
        __syncthreads();
    }
    float inv = rsqrtf(red[0] * (1.f / 1024.f) + 1e-5f);
    float4 g4 = reinterpret_cast<const float4*>(g)[t];
    float4 b4 = reinterpret_cast<const float4*>(b)[t];
    float4 o4;
    o4.x = dx * inv * g4.x + b4.x;
    o4.y = dy * inv * g4.y + b4.y;
    o4.z = dz * inv * g4.z + b4.z;
    o4.w = dw * inv * g4.w + b4.w;
    reinterpret_cast<float4*>(out + row * 1024)[t] = o4;
    if (ohi != nullptr) {
        __nv_bfloat16 h0, h1, h2, h3, l0, l1, l2, l3;
        split_bf16(o4.x, h0, l0); split_bf16(o4.y, h1, l1);
        split_bf16(o4.z, h2, l2); split_bf16(o4.w, h3, l3);
        __nv_bfloat162 p0, p1;
        p0.x = h0; p0.y = h1; p1.x = h2; p1.y = h3;
        reinterpret_cast<__nv_bfloat162*>(ohi + row * 1024)[2 * t]     = p0;
        reinterpret_cast<__nv_bfloat162*>(ohi + row * 1024)[2 * t + 1] = p1;
        p0.x = l0; p0.y = l1; p1.x = l2; p1.y = l3;
        reinterpret_cast<__nv_bfloat162*>(olo + row * 1024)[2 * t]     = p0;
        reinterpret_cast<__nv_bfloat162*>(olo + row * 1024)[2 * t + 1] = p1;
    }
}

// ---------------------------------------------------------------------------
// Host orchestration
// ---------------------------------------------------------------------------
extern "C" void kernel_launch(void* const* d_in, const int* in_sizes, int n_in,
                              void* d_out, int out_size) {
    (void)in_sizes; (void)n_in; (void)out_size;
    const float* x    = (const float*)d_in[0];
    const float* Wqkv = (const float*)d_in[1];
    const float* bqkv = (const float*)d_in[2];
    const float* Wo   = (const float*)d_in[3];
    const float* bo   = (const float*)d_in[4];
    const float* W1   = (const float*)d_in[5];
    const float* b1   = (const float*)d_in[6];
    const float* W2   = (const float*)d_in[7];
    const float* b2   = (const float*)d_in[8];
    const float* ln1g = (const float*)d_in[9];
    const float* ln1b = (const float*)d_in[10];
    const float* ln2g = (const float*)d_in[11];
    const float* ln2b = (const float*)d_in[12];
    const float* lnfg = (const float*)d_in[13];
    const float* lnfb = (const float*)d_in[14];
    const float* Wout = (const float*)d_in[15];
    const float* bout = (const float*)d_in[16];
    float* out = (float*)d_out;

    float *h, *tmp;
    __nv_bfloat16 *hhi, *hlo, *bhi, *blo, *whi, *wlo, *qvh, *qvl;
    cudaGetSymbolAddress((void**)&h,   g_h);
    cudaGetSymbolAddress((void**)&tmp, g_tmp);
    cudaGetSymbolAddress((void**)&hhi, g_hhi);
    cudaGetSymbolAddress((void**)&hlo, g_hlo);
    cudaGetSymbolAddress((void**)&bhi, g_bhi);
    cudaGetSymbolAddress((void**)&blo, g_blo);
    cudaGetSymbolAddress((void**)&whi, g_whi);
    cudaGetSymbolAddress((void**)&wlo, g_wlo);
    cudaGetSymbolAddress((void**)&qvh, g_qkvhi);
    cudaGetSymbolAddress((void**)&qvl, g_qkvlo);

    cudaFuncSetAttribute(gemm_mma<0, 0, 0>, cudaFuncAttributeMaxDynamicSharedMemorySize, GEMM_SMEM);
    cudaFuncSetAttribute(gemm_mma<0, 0, 1>, cudaFuncAttributeMaxDynamicSharedMemorySize, GEMM_SMEM);
    cudaFuncSetAttribute(gemm_mma<1, 0, 1>, cudaFuncAttributeMaxDynamicSharedMemorySize, GEMM_SMEM);
    cudaFuncSetAttribute(gemm_mma<0, 1, 0>, cudaFuncAttributeMaxDynamicSharedMemorySize, GEMM_SMEM);
    cudaFuncSetAttribute(attn_mma_kernel, cudaFuncAttributeMaxDynamicSharedMemorySize, ATTN_SMEM);

    // weight splits
    cvt_split_kernel<<<12288, 256>>>(Wqkv, whi + OFF_QKV, wlo + OFF_QKV, 3145728);
    cvt_split_kernel<<<4096, 256>>>(Wo,   whi + OFF_WO,   wlo + OFF_WO,  1048576);
    cvt_split_kernel<<<8192, 256>>>(W1,   whi + OFF_W1,   wlo + OFF_W1,  2097152);
    cvt_split_kernel<<<8192, 256>>>(W2,   whi + OFF_W2,   wlo + OFF_W2,  2097152);
    cvt_split_kernel<<<512, 256>>>(Wout,  whi + OFF_WOUT, wlo + OFF_WOUT, 131072);

    add_pe_kernel<<<(TTT * DDD) / 256, 256>>>(x, h, hhi, hlo);

    for (int l = 0; l < LLL; l++) {
        const __nv_bfloat16* wq_h = whi + OFF_QKV + (size_t)l * 3145728;
        const __nv_bfloat16* wq_l = wlo + OFF_QKV + (size_t)l * 3145728;
        const __nv_bfloat16* wo_h = whi + OFF_WO + (size_t)l * 1048576;
        const __nv_bfloat16* wo_l = wlo + OFF_WO + (size_t)l * 1048576;
        const __nv_bfloat16* w1_h = whi + OFF_W1 + (size_t)l * 2097152;
        const __nv_bfloat16* w1_l = wlo + OFF_W1 + (size_t)l * 2097152;
        const __nv_bfloat16* w2_h = whi + OFF_W2 + (size_t)l * 2097152;
        const __nv_bfloat16* w2_l = wlo + OFF_W2 + (size_t)l * 2097152;

        // qkv (bf16 split) = h @ Wqkv^T + bqkv
        gemm_mma<0, 0, 1><<<dim3(3072 / 128, TTT / 128), 256, GEMM_SMEM>>>(
            hhi, hlo, wq_h, wq_l, bqkv + (size_t)l * 3072, nullptr, qvh, qvl,
            TTT, 3072, 1024);
        // ctx (bf16 split) = flash attention (HMMA)
        attn_mma_kernel<<<dim3(SSS / 128, BBB * HHH), 256, ATTN_SMEM>>>(
            qvh, qvl, bhi, blo);
        // tmp = ctx @ Wo^T + bo
        gemm_mma<0, 0, 0><<<dim3(1024 / 128, TTT / 128), 256, GEMM_SMEM>>>(
            bhi, blo, wo_h, wo_l, bo + (size_t)l * 1024, tmp, nullptr, nullptr,
            TTT, 1024, 1024);
        // h = LN(h + tmp), emit split
        ln_kernel<<<TTT, 256>>>(h, tmp, ln1g + (size_t)l * 1024, ln1b + (size_t)l * 1024,
                                h, hhi, hlo);
        // ff (bf16 split) = relu(h @ W1^T + b1)
        gemm_mma<1, 0, 1><<<dim3(2048 / 128, TTT / 128), 256, GEMM_SMEM>>>(
            hhi, hlo, w1_h, w1_l, b1 + (size_t)l * 2048, nullptr, bhi, blo,
            TTT, 2048, 1024);
        // tmp = ff @ W2^T + b2
        gemm_mma<0, 0, 0><<<dim3(1024 / 128, TTT / 128), 256, GEMM_SMEM>>>(
            bhi, blo, w2_h, w2_l, b2 + (size_t)l * 1024, tmp, nullptr, nullptr,
            TTT, 1024, 2048);
        // h = LN(h + ff2), emit split
        ln_kernel<<<TTT, 256>>>(h, tmp, ln2g + (size_t)l * 1024, ln2b + (size_t)l * 1024,
                                h, hhi, hlo);
    }

    ln_kernel<<<TTT, 256>>>(h, nullptr, lnfg, lnfb, h, hhi, hlo);
    gemm_mma<0, 1, 0><<<dim3(DMEMM / 128, TTT / 128), 256, GEMM_SMEM>>>(
        hhi, hlo, whi + OFF_WOUT, wlo + OFF_WOUT, bout, out, nullptr, nullptr,
        TTT, DMEMM, 1024);
}

// round 5
// speedup vs baseline: 3.2209x; 1.1911x over previous
#include <cuda_runtime.h>
#include <cuda_bf16.h>
#include <math.h>
#include <stdint.h>

// Problem constants
#define BBB 32
#define SSS 512
#define DDD 1024
#define HHH 16
#define DHH 64
#define LLL 4
#define DFFF 2048
#define DMEMM 512
#define TTT (BBB * SSS)   // 16384 tokens

// ---------------------------------------------------------------------------
// Scratch (static device globals — no allocation at runtime)
// ---------------------------------------------------------------------------
__device__ float g_h[(size_t)TTT * DDD];              //  64 MB
__device__ float g_tmp[(size_t)TTT * DDD];            //  64 MB
__device__ float g_pe[(size_t)SSS * DDD];             //   2 MB  PE table
__device__ __nv_bfloat16 g_hhi[(size_t)TTT * DDD];    //  32 MB
__device__ __nv_bfloat16 g_hlo[(size_t)TTT * DDD];
__device__ __nv_bfloat16 g_bhi[(size_t)TTT * DFFF];   //  64 MB  ctx / ff split
__device__ __nv_bfloat16 g_blo[(size_t)TTT * DFFF];
__device__ __nv_bfloat16 g_qkvhi[(size_t)TTT * 3 * DDD];  // 96 MB
__device__ __nv_bfloat16 g_qkvlo[(size_t)TTT * 3 * DDD];  // 96 MB
#define WTOT 34078720ULL
__device__ __nv_bfloat16 g_whi[WTOT];
__device__ __nv_bfloat16 g_wlo[WTOT];

#define OFF_QKV 0ULL
#define OFF_WO  12582912ULL
#define OFF_W1  16777216ULL
#define OFF_W2  25165824ULL
#define OFF_WOUT 33554432ULL

// ---------------------------------------------------------------------------
// PTX helpers (baseline sm_80+: mma.sync / ldmatrix / cp.async)
// ---------------------------------------------------------------------------
__device__ __forceinline__ uint32_t smem_u32(const void* p) {
    uint32_t a;
    asm("{ .reg .u64 t; cvta.to.shared.u64 t, %1; cvt.u32.u64 %0, t; }" : "=r"(a) : "l"(p));
    return a;
}

#define CP16(saddr, gptr) \
    asm volatile("cp.async.cg.shared.global [%0], [%1], 16;" :: "r"(saddr), "l"(gptr))
#define CPCOMMIT() asm volatile("cp.async.commit_group;" ::: "memory")
#define CPWAIT(n)  asm volatile("cp.async.wait_group %0;" :: "n"(n) : "memory")

#define LDSM4(r, addr)                                                          \
    asm volatile("ldmatrix.sync.aligned.m8n8.x4.shared.b16 {%0,%1,%2,%3}, [%4];" \
        : "=r"((r)[0]), "=r"((r)[1]), "=r"((r)[2]), "=r"((r)[3]) : "r"(addr))

#define LDSM4T(r, addr)                                                          \
    asm volatile("ldmatrix.sync.aligned.m8n8.x4.trans.shared.b16 {%0,%1,%2,%3}, [%4];" \
        : "=r"((r)[0]), "=r"((r)[1]), "=r"((r)[2]), "=r"((r)[3]) : "r"(addr))

#define MMA_BF16(d, a, b0v, b1v)                                                \
    asm volatile("mma.sync.aligned.m16n8k16.row.col.f32.bf16.bf16.f32 "         \
        "{%0,%1,%2,%3}, {%4,%5,%6,%7}, {%8,%9}, {%0,%1,%2,%3};"                 \
        : "+f"((d)[0]), "+f"((d)[1]), "+f"((d)[2]), "+f"((d)[3])                \
        : "r"((a)[0]), "r"((a)[1]), "r"((a)[2]), "r"((a)[3]), "r"(b0v), "r"(b1v))

__device__ __forceinline__ void split_bf16(float v, __nv_bfloat16& h, __nv_bfloat16& l) {
    h = __float2bfloat16(v);
    l = __float2bfloat16(v - __bfloat162float(h));
}
__device__ __forceinline__ uint32_t pack_hi2(float a, float b) {
    uint32_t r;
    asm("cvt.rn.bf16x2.f32 %0, %1, %2;" : "=r"(r) : "f"(b), "f"(a));
    return r;
}
__device__ __forceinline__ float bf_round(float v) {
    return __bfloat162float(__float2bfloat16(v));
}

// ---------------------------------------------------------------------------
// 0) merged weight split: all 5 weights, one launch.
//    Destination is contiguous: dst elem offset = 4 * global f4 index.
// ---------------------------------------------------------------------------
#define F4_QKV 3145728
#define F4_WO  (F4_QKV + 1048576)   // 4194304
#define F4_W1  (F4_WO + 2097152)    // 6291456
#define F4_W2  (F4_W1 + 2097152)    // 8388608
#define F4_ALL (F4_W2 + 131072)     // 8519680

__global__ __launch_bounds__(256)
void cvt_split_all(const float* __restrict__ Wqkv, const float* __restrict__ Wo,
                   const float* __restrict__ W1, const float* __restrict__ W2,
                   const float* __restrict__ Wout,
                   __nv_bfloat16* __restrict__ hi, __nv_bfloat16* __restrict__ lo) {
    int i = blockIdx.x * 256 + threadIdx.x;
    if (i >= F4_ALL) return;
    const float* src;
    int li;
    if (i < F4_QKV)      { src = Wqkv; li = i; }
    else if (i < F4_WO)  { src = Wo;   li = i - F4_QKV; }
    else if (i < F4_W1)  { src = W1;   li = i - F4_WO; }
    else if (i < F4_W2)  { src = W2;   li = i - F4_W1; }
    else                 { src = Wout; li = i - F4_W2; }
    float4 v = reinterpret_cast<const float4*>(src)[li];
    __nv_bfloat16 h0, h1, h2, h3, l0, l1, l2, l3;
    split_bf16(v.x, h0, l0); split_bf16(v.y, h1, l1);
    split_bf16(v.z, h2, l2); split_bf16(v.w, h3, l3);
    __nv_bfloat162 a, b;
    a.x = h0; a.y = h1; b.x = h2; b.y = h3;
    reinterpret_cast<__nv_bfloat162*>(hi)[2 * i]     = a;
    reinterpret_cast<__nv_bfloat162*>(hi)[2 * i + 1] = b;
    a.x = l0; a.y = l1; b.x = l2; b.y = l3;
    reinterpret_cast<__nv_bfloat162*>(lo)[2 * i]     = a;
    reinterpret_cast<__nv_bfloat162*>(lo)[2 * i + 1] = b;
}

// ---------------------------------------------------------------------------
// 1a) PE table: pe[s,d]   (one-time MUFU cost)
// ---------------------------------------------------------------------------
__global__ __launch_bounds__(256)
void pe_table_kernel(float* __restrict__ pe) {
    int idx = blockIdx.x * 256 + threadIdx.x;   // SSS*DDD = 524288
    int d = idx & (DDD - 1);
    int s = idx >> 10;
    float div = expf((float)(d & ~1) * (-9.2103403719761836f / (float)DDD));
    float ang = (float)s * div;
    pe[idx] = (d & 1) ? cosf(ang) : sinf(ang);
}

// ---------------------------------------------------------------------------
// 1b) h[s,b,:] = x[b,s,:] + PE[s,:]   (float4 streaming, + split emit)
// ---------------------------------------------------------------------------
__global__ __launch_bounds__(256)
void add_pe_kernel(const float* __restrict__ x, const float* __restrict__ pe,
                   float* __restrict__ h,
                   __nv_bfloat16* __restrict__ hhi, __nv_bfloat16* __restrict__ hlo) {
    int i4 = blockIdx.x * 256 + threadIdx.x;     // over TTT*DDD/4
    int d4  = i4 & 255;                          // float4 index within row
    int row = i4 >> 8;                           // s*B + b
    int s   = row >> 5;
    int b   = row & 31;
    float4 xv = reinterpret_cast<const float4*>(x)[((size_t)(b * SSS + s) << 8) + d4];
    float4 pv = reinterpret_cast<const float4*>(pe)[((size_t)s << 8) + d4];
    float4 v;
    v.x = xv.x + pv.x; v.y = xv.y + pv.y; v.z = xv.z + pv.z; v.w = xv.w + pv.w;
    reinterpret_cast<float4*>(h)[i4] = v;
    __nv_bfloat16 h0, h1, h2, h3, l0, l1, l2, l3;
    split_bf16(v.x, h0, l0); split_bf16(v.y, h1, l1);
    split_bf16(v.z, h2, l2); split_bf16(v.w, h3, l3);
    __nv_bfloat162 p0, p1;
    p0.x = h0; p0.y = h1; p1.x = h2; p1.y = h3;
    reinterpret_cast<__nv_bfloat162*>(hhi)[2 * i4]     = p0;
    reinterpret_cast<__nv_bfloat162*>(hhi)[2 * i4 + 1] = p1;
    p0.x = l0; p0.y = l1; p1.x = l2; p1.y = l3;
    reinterpret_cast<__nv_bfloat162*>(hlo)[2 * i4]     = p0;
    reinterpret_cast<__nv_bfloat162*>(hlo)[2 * i4 + 1] = p1;
}

// ---------------------------------------------------------------------------
// 2) HMMA GEMM (bf16x3); now 2 CTAs/SM
// ---------------------------------------------------------------------------
#define SROWB 80
#define A_HI 0u
#define A_LO 10240u
#define W_HI 20480u
#define W_LO 30720u
#define STAGE_B 40960u
#define GEMM_SMEM (2 * 40960)

template <int PERM>
__device__ __forceinline__ void load_stage(
    uint32_t sbase,
    const __nv_bfloat16* __restrict__ Ahi, const __nv_bfloat16* __restrict__ Alo,
    const __nv_bfloat16* __restrict__ Whi, const __nv_bfloat16* __restrict__ Wlo,
    int m0, int n0, int K, int k0, int t) {
#pragma unroll
    for (int i = 0; i < 2; ++i) {
        int u = t + i * 256;
        int row = u >> 2, c8 = u & 3;
        int garow = m0 + row;
        if (PERM) garow = ((garow & 511) << 5) | (garow >> 9);
        const __nv_bfloat16* pa_hi = Ahi + (size_t)garow * K + k0 + c8 * 8;
        const __nv_bfloat16* pa_lo = Alo + (size_t)garow * K + k0 + c8 * 8;
        const __nv_bfloat16* pw_hi = Whi + (size_t)(n0 + row) * K + k0 + c8 * 8;
        const __nv_bfloat16* pw_lo = Wlo + (size_t)(n0 + row) * K + k0 + c8 * 8;
        uint32_t d = (uint32_t)(row * SROWB + c8 * 16);
        CP16(sbase + A_HI + d, pa_hi);
        CP16(sbase + A_LO + d, pa_lo);
        CP16(sbase + W_HI + d, pw_hi);
        CP16(sbase + W_LO + d, pw_lo);
    }
}

template <int RELU, int PERM, int SPLIT>
__global__ __launch_bounds__(256, 2)
void gemm_mma(const __nv_bfloat16* __restrict__ Ahi, const __nv_bfloat16* __restrict__ Alo,
              const __nv_bfloat16* __restrict__ Whi, const __nv_bfloat16* __restrict__ Wlo,
              const float* __restrict__ bias, float* __restrict__ C,
              __nv_bfloat16* __restrict__ Chi, __nv_bfloat16* __restrict__ Clo,
              int M, int N, int K) {
    extern __shared__ char smem[];
    const uint32_t sb = smem_u32(smem);
    const int t    = threadIdx.x;
    const int lane = t & 31;
    const int w    = t >> 5;
    const int wm   = w & 1;
    const int wn   = w >> 1;
    const int m0   = blockIdx.y * 128;
    const int n0   = blockIdx.x * 128;

    float acc[4][4][4];
#pragma unroll
    for (int a = 0; a < 4; a++)
#pragma unroll
        for (int b = 0; b < 4; b++)
#pragma unroll
            for (int c = 0; c < 4; c++) acc[a][b][c] = 0.f;

    const uint32_t a_off = (uint32_t)((wm * 64 + (lane & 15)) * SROWB + (lane >> 4) * 16);
    const int brow = wn * 32 + (lane & 7) + ((lane & 16) >> 1);
    const uint32_t b_off = (uint32_t)(brow * SROWB + ((lane >> 3) & 1) * 16);

    const int NC = K >> 5;
    load_stage<PERM>(sb, Ahi, Alo, Whi, Wlo, m0, n0, K, 0, t);
    CPCOMMIT();

    for (int c = 0; c < NC; ++c) {
        const uint32_t stb = sb + (uint32_t)(c & 1) * STAGE_B;
        if (c + 1 < NC) {
            load_stage<PERM>(sb + (uint32_t)((c + 1) & 1) * STAGE_B,
                             Ahi, Alo, Whi, Wlo, m0, n0, K, (c + 1) << 5, t);
            CPCOMMIT();
            CPWAIT(1);
        } else {
            CPWAIT(0);
        }
        __syncthreads();
#pragma unroll
        for (int ks = 0; ks < 2; ++ks) {
            const uint32_t ao = stb + a_off + ks * 32;
            const uint32_t bo = stb + b_off + ks * 32;
            uint32_t fa_hi[4][4], fa_lo[4][4];
#pragma unroll
            for (int mi = 0; mi < 4; ++mi) {
                LDSM4(fa_hi[mi], ao + A_HI + mi * (16 * SROWB));
                LDSM4(fa_lo[mi], ao + A_LO + mi * (16 * SROWB));
            }
            uint32_t fb_hi[2][4], fb_lo[2][4];
#pragma unroll
            for (int nj = 0; nj < 2; ++nj) {
                LDSM4(fb_hi[nj], bo + W_HI + nj * (16 * SROWB));
                LDSM4(fb_lo[nj], bo + W_LO + nj * (16 * SROWB));
            }
#pragma unroll
            for (int mi = 0; mi < 4; ++mi)
#pragma unroll
                for (int ni = 0; ni < 4; ++ni) {
                    const int nj = ni >> 1, kk = (ni & 1) * 2;
                    MMA_BF16(acc[mi][ni], fa_hi[mi], fb_hi[nj][kk], fb_hi[nj][kk + 1]);
                    MMA_BF16(acc[mi][ni], fa_hi[mi], fb_lo[nj][kk], fb_lo[nj][kk + 1]);
                    MMA_BF16(acc[mi][ni], fa_lo[mi], fb_hi[nj][kk], fb_hi[nj][kk + 1]);
                }
        }
        __syncthreads();
    }

    const int qrow = lane >> 2;
    const int qcol = (lane & 3) * 2;
#pragma unroll
    for (int mi = 0; mi < 4; ++mi) {
        const int row0 = m0 + wm * 64 + mi * 16 + qrow;
#pragma unroll
        for (int ni = 0; ni < 4; ++ni) {
            const int col = n0 + wn * 32 + ni * 8 + qcol;
            const float bb0 = bias[col];
            const float bb1 = bias[col + 1];
            float v00 = acc[mi][ni][0] + bb0;
            float v01 = acc[mi][ni][1] + bb1;
            float v10 = acc[mi][ni][2] + bb0;
            float v11 = acc[mi][ni][3] + bb1;
            if (RELU) {
                v00 = fmaxf(v00, 0.f); v01 = fmaxf(v01, 0.f);
                v10 = fmaxf(v10, 0.f); v11 = fmaxf(v11, 0.f);
            }
            if (SPLIT) {
                __nv_bfloat16 h0, l0, h1, l1;
                __nv_bfloat162 hh, ll;
                split_bf16(v00, h0, l0); split_bf16(v01, h1, l1);
                hh.x = h0; hh.y = h1; ll.x = l0; ll.y = l1;
                *reinterpret_cast<__nv_bfloat162*>(Chi + (size_t)row0 * N + col) = hh;
                *reinterpret_cast<__nv_bfloat162*>(Clo + (size_t)row0 * N + col) = ll;
                split_bf16(v10, h0, l0); split_bf16(v11, h1, l1);
                hh.x = h0; hh.y = h1; ll.x = l0; ll.y = l1;
                *reinterpret_cast<__nv_bfloat162*>(Chi + (size_t)(row0 + 8) * N + col) = hh;
                *reinterpret_cast<__nv_bfloat162*>(Clo + (size_t)(row0 + 8) * N + col) = ll;
            } else {
                *reinterpret_cast<float2*>(C + (size_t)row0 * N + col) =
                    make_float2(v00, v01);
                *reinterpret_cast<float2*>(C + (size_t)(row0 + 8) * N + col) =
                    make_float2(v10, v11);
            }
        }
    }
}

// ---------------------------------------------------------------------------
// 3) HMMA flash attention, bf16x3 compensated (unchanged from round 4)
// ---------------------------------------------------------------------------
#define AROWB 144
#define AQ_HI 0u
#define AQ_LO 18432u
#define AST0  36864u
#define ASTG  36864u
#define AK_HI 0u
#define AK_LO 9216u
#define AV_HI 18432u
#define AV_LO 27648u
#define ATTN_SMEM (36864 + 2 * 36864)

__device__ __forceinline__ void attn_load_kv(
    uint32_t sbase, const __nv_bfloat16* __restrict__ qhi,
    const __nv_bfloat16* __restrict__ qlo, int b, int hd, int kt, int t) {
#pragma unroll
    for (int i = 0; i < 8; ++i) {
        int u = t + i * 256;
        int sel = u >> 9;
        int v = u & 511;
        int row = v >> 3, seg = v & 7;
        const __nv_bfloat16* base = (sel & 1) ? qlo : qhi;
        int off = (sel >> 1) ? 2048 : 1024;
        const __nv_bfloat16* src =
            base + ((size_t)((kt * 64 + row) * BBB + b)) * 3072 + off + hd + seg * 8;
        uint32_t dst = sbase + (uint32_t)sel * 9216u + (uint32_t)(row * AROWB + seg * 16);
        CP16(dst, src);
    }
}

__global__ __launch_bounds__(256, 2)
void attn_mma_kernel(const __nv_bfloat16* __restrict__ qhi,
                     const __nv_bfloat16* __restrict__ qlo,
                     __nv_bfloat16* __restrict__ chi, __nv_bfloat16* __restrict__ clo) {
    extern __shared__ char smem[];
    const uint32_t sb = smem_u32(smem);
    const int t    = threadIdx.x;
    const int lane = t & 31;
    const int w    = t >> 5;
    const int b    = blockIdx.y >> 4;
    const int h    = blockIdx.y & 15;
    const int q0   = blockIdx.x * 128;
    const int hd   = h * DHH;

#pragma unroll
    for (int i = 0; i < 8; ++i) {
        int u = t + i * 256;
        int ishi = (u < 1024);
        int v = u & 1023;
        int row = v >> 3, seg = v & 7;
        const __nv_bfloat16* src = (ishi ? qhi : qlo) +
            ((size_t)((q0 + row) * BBB + b)) * 3072 + hd + seg * 8;
        uint32_t dst = sb + (ishi ? AQ_HI : AQ_LO) + (uint32_t)(row * AROWB + seg * 16);
        CP16(dst, src);
    }
    CPCOMMIT();
    attn_load_kv(sb + AST0, qhi, qlo, b, hd, 0, t);
    CPCOMMIT();

    float Oa[8][4];
#pragma unroll
    for (int j = 0; j < 8; j++)
#pragma unroll
        for (int c = 0; c < 4; c++) Oa[j][c] = 0.f;
    float m0r = -1e30f, m1r = -1e30f, l0r = 0.f, l1r = 0.f;

    const uint32_t arow_off = (uint32_t)((w * 16 + (lane & 15)) * AROWB + (lane >> 4) * 16);
    const uint32_t brow_off = (uint32_t)(((lane & 7) + ((lane & 16) >> 1)) * AROWB +
                                         ((lane >> 3) & 1) * 16);
    const uint32_t vrow_off = (uint32_t)((lane & 15) * AROWB + (lane >> 4) * 16);

    for (int kt = 0; kt < 8; ++kt) {
        CPWAIT(0);
        __syncthreads();
        if (kt + 1 < 8) {
            attn_load_kv(sb + AST0 + (uint32_t)((kt + 1) & 1) * ASTG, qhi, qlo, b, hd,
                         kt + 1, t);
            CPCOMMIT();
        }
        const uint32_t stg = sb + AST0 + (uint32_t)(kt & 1) * ASTG;

        float st[8][4];
#pragma unroll
        for (int j = 0; j < 8; j++)
#pragma unroll
            for (int c = 0; c < 4; c++) st[j][c] = 0.f;
#pragma unroll
        for (int pass = 0; pass < 3; ++pass) {
            const uint32_t abase = sb + (pass == 2 ? AQ_LO : AQ_HI) + arow_off;
            const uint32_t bbase = stg + (pass == 1 ? AK_LO : AK_HI) + brow_off;
#pragma unroll
            for (int kc = 0; kc < 4; ++kc) {
                uint32_t fa[4];
                LDSM4(fa, abase + kc * 32);
#pragma unroll
                for (int g = 0; g < 4; ++g) {
                    uint32_t fb[4];
                    LDSM4(fb, bbase + g * (16 * AROWB) + kc * 32);
                    MMA_BF16(st[2 * g],     fa, fb[0], fb[1]);
                    MMA_BF16(st[2 * g + 1], fa, fb[2], fb[3]);
                }
            }
        }

        float mx0 = -1e30f, mx1 = -1e30f;
#pragma unroll
        for (int j = 0; j < 8; j++) {
            st[j][0] *= 0.125f; st[j][1] *= 0.125f;
            st[j][2] *= 0.125f; st[j][3] *= 0.125f;
            mx0 = fmaxf(mx0, fmaxf(st[j][0], st[j][1]));
            mx1 = fmaxf(mx1, fmaxf(st[j][2], st[j][3]));
        }
        mx0 = fmaxf(mx0, __shfl_xor_sync(0xffffffffu, mx0, 1));
        mx0 = fmaxf(mx0, __shfl_xor_sync(0xffffffffu, mx0, 2));
        mx1 = fmaxf(mx1, __shfl_xor_sync(0xffffffffu, mx1, 1));
        mx1 = fmaxf(mx1, __shfl_xor_sync(0xffffffffu, mx1, 2));
        const float nm0 = fmaxf(m0r, mx0), nm1 = fmaxf(m1r, mx1);
        const float al0 = __expf(m0r - nm0), al1 = __expf(m1r - nm1);
        float s0 = 0.f, s1 = 0.f;
#pragma unroll
        for (int j = 0; j < 8; j++) {
            st[j][0] = __expf(st[j][0] - nm0);
            st[j][1] = __expf(st[j][1] - nm0);
            st[j][2] = __expf(st[j][2] - nm1);
            st[j][3] = __expf(st[j][3] - nm1);
            s0 += st[j][0] + st[j][1];
            s1 += st[j][2] + st[j][3];
        }
        s0 += __shfl_xor_sync(0xffffffffu, s0, 1);
        s0 += __shfl_xor_sync(0xffffffffu, s0, 2);
        s1 += __shfl_xor_sync(0xffffffffu, s1, 1);
        s1 += __shfl_xor_sync(0xffffffffu, s1, 2);
        l0r = l0r * al0 + s0;
        l1r = l1r * al1 + s1;
        m0r = nm0; m1r = nm1;
#pragma unroll
        for (int j = 0; j < 8; j++) {
            Oa[j][0] *= al0; Oa[j][1] *= al0;
            Oa[j][2] *= al1; Oa[j][3] *= al1;
        }

#pragma unroll
        for (int kc = 0; kc < 4; ++kc) {
            uint32_t ah[4], alo[4];
            {
                const float* p0 = st[2 * kc];
                const float* p1 = st[2 * kc + 1];
                ah[0] = pack_hi2(p0[0], p0[1]);
                ah[1] = pack_hi2(p0[2], p0[3]);
                ah[2] = pack_hi2(p1[0], p1[1]);
                ah[3] = pack_hi2(p1[2], p1[3]);
                alo[0] = pack_hi2(p0[0] - bf_round(p0[0]), p0[1] - bf_round(p0[1]));
                alo[1] = pack_hi2(p0[2] - bf_round(p0[2]), p0[3] - bf_round(p0[3]));
                alo[2] = pack_hi2(p1[0] - bf_round(p1[0]), p1[1] - bf_round(p1[1]));
                alo[3] = pack_hi2(p1[2] - bf_round(p1[2]), p1[3] - bf_round(p1[3]));
            }
            const uint32_t vbase = stg + (uint32_t)(kc * 16 * AROWB) + vrow_off;
#pragma unroll
            for (int g = 0; g < 4; ++g) {
                uint32_t fvh[4], fvl[4];
                LDSM4T(fvh, vbase + AV_HI + g * 32);
                MMA_BF16(Oa[2 * g],     ah,  fvh[0], fvh[1]);
                MMA_BF16(Oa[2 * g + 1], ah,  fvh[2], fvh[3]);
                MMA_BF16(Oa[2 * g],     alo, fvh[0], fvh[1]);
                MMA_BF16(Oa[2 * g + 1], alo, fvh[2], fvh[3]);
                LDSM4T(fvl, vbase + AV_LO + g * 32);
                MMA_BF16(Oa[2 * g],     ah,  fvl[0], fvl[1]);
                MMA_BF16(Oa[2 * g + 1], ah,  fvl[2], fvl[3]);
            }
        }
    }

    const float inv0 = 1.f / l0r;
    const float inv1 = 1.f / l1r;
    const int r_lo = q0 + w * 16 + (lane >> 2);
    const int col0 = hd + (lane & 3) * 2;
#pragma unroll
    for (int j = 0; j < 8; j++) {
        const int col = col0 + j * 8;
        float v0 = Oa[j][0] * inv0, v1 = Oa[j][1] * inv0;
        float v2 = Oa[j][2] * inv1, v3 = Oa[j][3] * inv1;
        __nv_bfloat16 h0, l0, h1, l1;
        __nv_bfloat162 hh, ll;
        size_t o0 = ((size_t)(r_lo * BBB + b)) * 1024 + col;
        split_bf16(v0, h0, l0); split_bf16(v1, h1, l1);
        hh.x = h0; hh.y = h1; ll.x = l0; ll.y = l1;
        *reinterpret_cast<__nv_bfloat162*>(chi + o0) = hh;
        *reinterpret_cast<__nv_bfloat162*>(clo + o0) = ll;
        size_t o1 = ((size_t)((r_lo + 8) * BBB + b)) * 1024 + col;
        split_bf16(v2, h0, l0); split_bf16(v3, h1, l1);
        hh.x = h0; hh.y = h1; ll.x = l0; ll.y = l1;
        *reinterpret_cast<__nv_bfloat162*>(chi + o1) = hh;
        *reinterpret_cast<__nv_bfloat162*>(clo + o1) = ll;
    }
}

// ---------------------------------------------------------------------------
// 4) LayerNorm with warp-shuffle reductions (+ bf16 split emit)
// ---------------------------------------------------------------------------
__global__ __launch_bounds__(256)
void ln_kernel(const float* __restrict__ a, const float* __restrict__ r,
               const float* __restrict__ g, const float* __restrict__ b,
               float* __restrict__ out,
               __nv_bfloat16* __restrict__ ohi, __nv_bfloat16* __restrict__ olo) {
    __shared__ float red1[8];
    __shared__ float red2[8];
    const int t = threadIdx.x;
    const int lane = t & 31;
    const int w = t >> 5;
    const size_t row = blockIdx.x;
    float4 v = reinterpret_cast<const float4*>(a + row * 1024)[t];
    if (r != nullptr) {
        float4 rv = reinterpret_cast<const float4*>(r + row * 1024)[t];
        v.x += rv.x; v.y += rv.y; v.z += rv.z; v.w += rv.w;
    }
    float s = v.x + v.y + v.z + v.w;
#pragma unroll
    for (int o = 16; o > 0; o >>= 1) s += __shfl_xor_sync(0xffffffffu, s, o);
    if (lane == 0) red1[w] = s;
    __syncthreads();
    float mu = (red1[0] + red1[1] + red1[2] + red1[3] +
                red1[4] + red1[5] + red1[6] + red1[7]) * (1.f / 1024.f);
    float dx = v.x - mu, dy = v.y - mu, dz = v.z - mu, dw = v.w - mu;
    float q = dx * dx + dy * dy + dz * dz + dw * dw;
#pragma unroll
    for (int o = 16; o > 0; o >>= 1) q += __shfl_xor_sync(0xffffffffu, q, o);
    if (lane == 0) red2[w] = q;
    __syncthreads();
    float var = (red2[0] + red2[1] + red2[2] + red2[3] +
                 red2[4] + red2[5] + red2[6] + red2[7]) * (1.f / 1024.f);
    float inv = rsqrtf(var + 1e-5f);
    float4 g4 = reinterpret_cast<const float4*>(g)[t];
    float4 b4 = reinterpret_cast<const float4*>(b)[t];
    float4 o4;
    o4.x = dx * inv * g4.x + b4.x;
    o4.y = dy * inv * g4.y + b4.y;
    o4.z = dz * inv * g4.z + b4.z;
    o4.w = dw * inv * g4.w + b4.w;
    reinterpret_cast<float4*>(out + row * 1024)[t] = o4;
    if (ohi != nullptr) {
        __nv_bfloat16 h0, h1, h2, h3, l0, l1, l2, l3;
        split_bf16(o4.x, h0, l0); split_bf16(o4.y, h1, l1);
        split_bf16(o4.z, h2, l2); split_bf16(o4.w, h3, l3);
        __nv_bfloat162 p0, p1;
        p0.x = h0; p0.y = h1; p1.x = h2; p1.y = h3;
        reinterpret_cast<__nv_bfloat162*>(ohi + row * 1024)[2 * t]     = p0;
        reinterpret_cast<__nv_bfloat162*>(ohi + row * 1024)[2 * t + 1] = p1;
        p0.x = l0; p0.y = l1; p1.x = l2; p1.y = l3;
        reinterpret_cast<__nv_bfloat162*>(olo + row * 1024)[2 * t]     = p0;
        reinterpret_cast<__nv_bfloat162*>(olo + row * 1024)[2 * t + 1] = p1;
    }
}

// ---------------------------------------------------------------------------
// Host orchestration
// ---------------------------------------------------------------------------
extern "C" void kernel_launch(void* const* d_in, const int* in_sizes, int n_in,
                              void* d_out, int out_size) {
    (void)in_sizes; (void)n_in; (void)out_size;
    const float* x    = (const float*)d_in[0];
    const float* Wqkv = (const float*)d_in[1];
    const float* bqkv = (const float*)d_in[2];
    const float* Wo   = (const float*)d_in[3];
    const float* bo   = (const float*)d_in[4];
    const float* W1   = (const float*)d_in[5];
    const float* b1   = (const float*)d_in[6];
    const float* W2   = (const float*)d_in[7];
    const float* b2   = (const float*)d_in[8];
    const float* ln1g = (const float*)d_in[9];
    const float* ln1b = (const float*)d_in[10];
    const float* ln2g = (const float*)d_in[11];
    const float* ln2b = (const float*)d_in[12];
    const float* lnfg = (const float*)d_in[13];
    const float* lnfb = (const float*)d_in[14];
    const float* Wout = (const float*)d_in[15];
    const float* bout = (const float*)d_in[16];
    float* out = (float*)d_out;

    float *h, *tmp, *pe;
    __nv_bfloat16 *hhi, *hlo, *bhi, *blo, *whi, *wlo, *qvh, *qvl;
    cudaGetSymbolAddress((void**)&h,   g_h);
    cudaGetSymbolAddress((void**)&tmp, g_tmp);
    cudaGetSymbolAddress((void**)&pe,  g_pe);
    cudaGetSymbolAddress((void**)&hhi, g_hhi);
    cudaGetSymbolAddress((void**)&hlo, g_hlo);
    cudaGetSymbolAddress((void**)&bhi, g_bhi);
    cudaGetSymbolAddress((void**)&blo, g_blo);
    cudaGetSymbolAddress((void**)&whi, g_whi);
    cudaGetSymbolAddress((void**)&wlo, g_wlo);
    cudaGetSymbolAddress((void**)&qvh, g_qkvhi);
    cudaGetSymbolAddress((void**)&qvl, g_qkvlo);

    cudaFuncSetAttribute(gemm_mma<0, 0, 0>, cudaFuncAttributeMaxDynamicSharedMemorySize, GEMM_SMEM);
    cudaFuncSetAttribute(gemm_mma<0, 0, 1>, cudaFuncAttributeMaxDynamicSharedMemorySize, GEMM_SMEM);
    cudaFuncSetAttribute(gemm_mma<1, 0, 1>, cudaFuncAttributeMaxDynamicSharedMemorySize, GEMM_SMEM);
    cudaFuncSetAttribute(gemm_mma<0, 1, 0>, cudaFuncAttributeMaxDynamicSharedMemorySize, GEMM_SMEM);
    cudaFuncSetAttribute(attn_mma_kernel, cudaFuncAttributeMaxDynamicSharedMemorySize, ATTN_SMEM);

    // weight splits (one launch) + PE table
    cvt_split_all<<<(F4_ALL + 255) / 256, 256>>>(Wqkv, Wo, W1, W2, Wout, whi, wlo);
    pe_table_kernel<<<(SSS * DDD) / 256, 256>>>(pe);
    add_pe_kernel<<<(TTT * DDD / 4) / 256, 256>>>(x, pe, h, hhi, hlo);

    for (int l = 0; l < LLL; l++) {
        const __nv_bfloat16* wq_h = whi + OFF_QKV + (size_t)l * 3145728;
        const __nv_bfloat16* wq_l = wlo + OFF_QKV + (size_t)l * 3145728;
        const __nv_bfloat16* wo_h = whi + OFF_WO + (size_t)l * 1048576;
        const __nv_bfloat16* wo_l = wlo + OFF_WO + (size_t)l * 1048576;
        const __nv_bfloat16* w1_h = whi + OFF_W1 + (size_t)l * 2097152;
        const __nv_bfloat16* w1_l = wlo + OFF_W1 + (size_t)l * 2097152;
        const __nv_bfloat16* w2_h = whi + OFF_W2 + (size_t)l * 2097152;
        const __nv_bfloat16* w2_l = wlo + OFF_W2 + (size_t)l * 2097152;

        // qkv (bf16 split) = h @ Wqkv^T + bqkv
        gemm_mma<0, 0, 1><<<dim3(3072 / 128, TTT / 128), 256, GEMM_SMEM>>>(
            hhi, hlo, wq_h, wq_l, bqkv + (size_t)l * 3072, nullptr, qvh, qvl,
            TTT, 3072, 1024);
        // ctx (bf16 split) = flash attention (HMMA)
        attn_mma_kernel<<<dim3(SSS / 128, BBB * HHH), 256, ATTN_SMEM>>>(
            qvh, qvl, bhi, blo);
        // tmp = ctx @ Wo^T + bo
        gemm_mma<0, 0, 0><<<dim3(1024 / 128, TTT / 128), 256, GEMM_SMEM>>>(
            bhi, blo, wo_h, wo_l, bo + (size_t)l * 1024, tmp, nullptr, nullptr,
            TTT, 1024, 1024);
        // h = LN(h + tmp), emit split
        ln_kernel<<<TTT, 256>>>(h, tmp, ln1g + (size_t)l * 1024, ln1b + (size_t)l * 1024,
                                h, hhi, hlo);
        // ff (bf16 split) = relu(h @ W1^T + b1)
        gemm_mma<1, 0, 1><<<dim3(2048 / 128, TTT / 128), 256, GEMM_SMEM>>>(
            hhi, hlo, w1_h, w1_l, b1 + (size_t)l * 2048, nullptr, bhi, blo,
            TTT, 2048, 1024);
        // tmp = ff @ W2^T + b2
        gemm_mma<0, 0, 0><<<dim3(1024 / 128, TTT / 128), 256, GEMM_SMEM>>>(
            bhi, blo, w2_h, w2_l, b2 + (size_t)l * 1024, tmp, nullptr, nullptr,
            TTT, 1024, 2048);
        // h = LN(h + ff2), emit split
        ln_kernel<<<TTT, 256>>>(h, tmp, ln2g + (size_t)l * 1024, ln2b + (size_t)l * 1024,
                                h, hhi, hlo);
    }

    ln_kernel<<<TTT, 256>>>(h, nullptr, lnfg, lnfb, h, hhi, hlo);
    gemm_mma<0, 1, 0><<<dim3(DMEMM / 128, TTT / 128), 256, GEMM_SMEM>>>(
        hhi, hlo, whi + OFF_WOUT, wlo + OFF_WOUT, bout, out, nullptr, nullptr,
        TTT, DMEMM, 1024);
}